// round 12
// baseline (speedup 1.0000x reference)
#include <cuda_runtime.h>
#include <cuda_bf16.h>

#define BATCH 16
#define NPIX  4096   // 64*64
#define MPIX  1024   // 32*32

// ---------------- scratch (device globals; no allocation) ----------------
__device__ unsigned g_Wb[384 * 256];                            // [theta;phi;g] bf16x2 k-pairs
__device__ unsigned g_Wob[512 * 128];                           // w_o bf16x2 k-pairs
__device__ __nv_bfloat16 g_Yh[(size_t)BATCH * 384 * NPIX];      // projections bf16
__device__ __align__(16) unsigned g_phq[(size_t)BATCH * 32768]; // phi, uint4-frag layout
__device__ __align__(16) unsigned g_gq[(size_t)BATCH * 131072]; // g,   uint4-frag layout
__device__ unsigned g_Ob[(size_t)BATCH * 128 * NPIX];           // attn out bf16x2 [b][v2][n]

// ---------------- helpers ----------------
__device__ __forceinline__ unsigned packbf(float lo, float hi) {
    __nv_bfloat162 h = __floats2bfloat162_rn(lo, hi);
    return *(unsigned*)&h;
}
__device__ __forceinline__ float2 unpackbf(unsigned u) {
    __nv_bfloat162 h = *(__nv_bfloat162*)&u;
    return __bfloat1622float2(h);
}
__device__ __forceinline__ void mma_bf16(float* d, const unsigned* a, const unsigned* b,
                                         const float* c)
{
    asm volatile(
        "mma.sync.aligned.m16n8k16.row.col.f32.bf16.bf16.f32 "
        "{%0,%1,%2,%3}, {%4,%5,%6,%7}, {%8,%9}, {%10,%11,%12,%13};\n"
        : "=f"(d[0]), "=f"(d[1]), "=f"(d[2]), "=f"(d[3])
        : "r"(a[0]), "r"(a[1]), "r"(a[2]), "r"(a[3]),
          "r"(b[0]), "r"(b[1]),
          "f"(c[0]), "f"(c[1]), "f"(c[2]), "f"(c[3]));
}
__device__ __forceinline__ void ldsm_x4(unsigned* r, unsigned saddr) {
    asm volatile(
        "ldmatrix.sync.aligned.m8n8.x4.shared.b16 {%0,%1,%2,%3}, [%4];"
        : "=r"(r[0]), "=r"(r[1]), "=r"(r[2]), "=r"(r[3]) : "r"(saddr));
}
#define CP16(dst, src) \
    asm volatile("cp.async.cg.shared.global [%0], [%1], 16;\n" :: "r"(dst), "l"(src))

// ---------------- weight convert/concat -> bf16 pairs ----------------
__global__ void wcvt_kernel(const float* __restrict__ wt, const float* __restrict__ wp,
                            const float* __restrict__ wg, const float* __restrict__ wo)
{
    int t = blockIdx.x * blockDim.x + threadIdx.x;
    if (t < 384 * 256) {
        int row = t >> 8, k2 = t & 255;
        const float* src;
        if (row < 64)       src = wt + (size_t)row * 512;
        else if (row < 128) src = wp + (size_t)(row - 64) * 512;
        else                src = wg + (size_t)(row - 128) * 512;
        g_Wb[t] = packbf(src[2 * k2], src[2 * k2 + 1]);
    } else {
        int u = t - 384 * 256;
        if (u >= 512 * 128) return;
        int row = u >> 7, k2 = u & 127;
        g_Wob[u] = packbf(wo[(size_t)row * 256 + 2 * k2], wo[(size_t)row * 256 + 2 * k2 + 1]);
    }
}

#define ASU 20
#define BSU 136
#define PROJ_SMEM ((4 * 128 * ASU + 2 * 16 * BSU) * 4)
#define GASY_SMEM ((4 * 128 * ASU + 4 * 16 * BSU) * 4)

// ---------------- projection GEMM: 4-stage A cp.async, 2-deep B reg prefetch ----
// Yh[b] = bf16(Wcat @ x[b]);  M=384, K2=256, N=4096
__global__ void __launch_bounds__(256, 2) gemm_proj(
    const unsigned* __restrict__ A, const float* __restrict__ Xbase,
    __nv_bfloat16* __restrict__ Cbase, int M, int K2, int N)
{
    extern __shared__ unsigned sm[];
    unsigned* As = sm;                   // 4 x 128*ASU
    unsigned* Bs = sm + 4 * 128 * ASU;   // 2 x 16*BSU

    int b = blockIdx.z;
    const float* X = Xbase + (size_t)b * (2 * K2) * N;
    __nv_bfloat16* C = Cbase + (size_t)b * M * N;
    int m0 = blockIdx.y * 128;
    int n0 = blockIdx.x * 128;

    int tx   = threadIdx.x;
    int wid  = tx >> 5;
    int lane = tx & 31;
    int gid  = lane >> 2;
    int tig  = lane & 3;
    int wm0  = (wid & 1) * 64;
    int wn0  = (wid >> 1) * 32;
    int lr   = (lane & 7) + ((lane >> 3) & 1) * 8;
    int lkc  = (lane >> 4) * 4;

    unsigned as_sb = (unsigned)__cvta_generic_to_shared(As);

    const int NT = K2 / 16;

    int bkr[2], bn4[2];
#pragma unroll
    for (int r = 0; r < 2; r++) {
        int idx = tx + 256 * r;
        bkr[r] = idx >> 5;
        bn4[r] = (idx & 31) * 4;
    }

    float acc[4][4][4];
#pragma unroll
    for (int i = 0; i < 4; i++)
#pragma unroll
        for (int j = 0; j < 4; j++)
#pragma unroll
            for (int q = 0; q < 4; q++) acc[i][j][q] = 0.f;

    float4 breg[2][2][2];   // [set][r][row0/1]
    auto ldgB = [&](int t, int set) {
        if (t >= NT) return;
#pragma unroll
        for (int r = 0; r < 2; r++) {
            const float* p0 = &X[(size_t)(2 * (t * 16 + bkr[r])) * N + n0 + bn4[r]];
            breg[set][r][0] = *(const float4*)p0;
            breg[set][r][1] = *(const float4*)(p0 + N);
        }
    };
    auto stageA = [&](int t) {
        if (t < NT) {
            int p = t & 3;
#pragma unroll
            for (int r = 0; r < 2; r++) {
                int idx = tx + 256 * r;
                int am = idx >> 2, c4 = (idx & 3) * 4;
                CP16(as_sb + (p * 128 * ASU + am * ASU + c4) * 4,
                     (const void*)&A[(size_t)(m0 + am) * K2 + t * 16 + c4]);
            }
        }
        asm volatile("cp.async.commit_group;\n");
    };

    ldgB(0, 0);
    ldgB(1, 1);
    stageA(0); stageA(1); stageA(2);

    for (int t = 0; t < NT; t++) {
        int pa = t & 3, pb = t & 1;
        __syncthreads();                  // all done reading tile t-1
        // STS B(t) from regs (loaded 2 iterations ago)
#pragma unroll
        for (int r = 0; r < 2; r++) {
            float4 u = breg[pb][r][0], w = breg[pb][r][1];
            uint4 pv = make_uint4(packbf(u.x, w.x), packbf(u.y, w.y),
                                  packbf(u.z, w.z), packbf(u.w, w.w));
            *(uint4*)&Bs[pb * 16 * BSU + bkr[r] * BSU + bn4[r]] = pv;
        }
        ldgB(t + 2, pb);                  // refill freed regset
        stageA(t + 3);
        asm volatile("cp.async.wait_group 3;\n");   // tile t's A arrived
        __syncthreads();                  // A + B tile t visible

#pragma unroll
        for (int s = 0; s < 2; s++) {
            unsigned af[4][4];
#pragma unroll
            for (int i = 0; i < 4; i++)
                ldsm_x4(af[i], as_sb + (pa * 128 * ASU + (wm0 + 16 * i + lr) * ASU + lkc) * 4 + s * 32);
            unsigned bfr[4][2];
#pragma unroll
            for (int j = 0; j < 4; j++) {
                int col = wn0 + 8 * j + gid;
                bfr[j][0] = Bs[pb * 16 * BSU + (8 * s + tig) * BSU + col];
                bfr[j][1] = Bs[pb * 16 * BSU + (8 * s + tig + 4) * BSU + col];
            }
#pragma unroll
            for (int i = 0; i < 4; i++)
#pragma unroll
                for (int j = 0; j < 4; j++)
                    mma_bf16(acc[i][j], af[i], bfr[j], acc[i][j]);
        }
    }

    // epilogue: write bf16 pairs
#pragma unroll
    for (int i = 0; i < 4; i++) {
        int r0 = m0 + wm0 + 16 * i + gid;
#pragma unroll
        for (int j = 0; j < 4; j++) {
            int cc = n0 + wn0 + 8 * j + 2 * tig;
            *(unsigned*)&C[(size_t)r0 * N + cc]       = packbf(acc[i][j][0], acc[i][j][1]);
            *(unsigned*)&C[(size_t)(r0 + 8) * N + cc] = packbf(acc[i][j][2], acc[i][j][3]);
        }
    }
}

// ---------------- final GEMM: 4-stage cp.async (A and B) ----------------
__global__ void __launch_bounds__(256, 2) gemm_async(
    const unsigned* __restrict__ A, const unsigned* __restrict__ Bbase,
    float* __restrict__ Cbase,
    int M, int K2, int N,
    const float* __restrict__ gamma, const float* __restrict__ resid)
{
    extern __shared__ unsigned sm[];
    unsigned* As = sm;                   // 4 x 128*ASU
    unsigned* Bs = sm + 4 * 128 * ASU;   // 4 x 16*BSU

    int b = blockIdx.z;
    const unsigned* B = Bbase + (size_t)b * K2 * N;
    float* C = Cbase + (size_t)b * M * N;
    int m0 = blockIdx.y * 128;
    int n0 = blockIdx.x * 128;

    int tx   = threadIdx.x;
    int wid  = tx >> 5;
    int lane = tx & 31;
    int gid  = lane >> 2;
    int tig  = lane & 3;
    int wm0  = (wid & 1) * 64;
    int wn0  = (wid >> 1) * 32;
    int lr   = (lane & 7) + ((lane >> 3) & 1) * 8;
    int lkc  = (lane >> 4) * 4;

    unsigned as_sb = (unsigned)__cvta_generic_to_shared(As);
    unsigned bs_sb = (unsigned)__cvta_generic_to_shared(Bs);

    const int NT = K2 / 16;

    float acc[4][4][4];
#pragma unroll
    for (int i = 0; i < 4; i++)
#pragma unroll
        for (int j = 0; j < 4; j++)
#pragma unroll
            for (int q = 0; q < 4; q++) acc[i][j][q] = 0.f;

    auto stage = [&](int t) {
        if (t < NT) {
            int p = t & 3;
#pragma unroll
            for (int r = 0; r < 2; r++) {
                int idx = tx + 256 * r;
                int am = idx >> 2, c4 = (idx & 3) * 4;
                CP16(as_sb + (p * 128 * ASU + am * ASU + c4) * 4,
                     (const void*)&A[(size_t)(m0 + am) * K2 + t * 16 + c4]);
                int kr = idx >> 5, n4 = (idx & 31) * 4;
                CP16(bs_sb + (p * 16 * BSU + kr * BSU + n4) * 4,
                     (const void*)&B[(size_t)(t * 16 + kr) * N + n0 + n4]);
            }
        }
        asm volatile("cp.async.commit_group;\n");
    };

    stage(0); stage(1); stage(2);

    for (int t = 0; t < NT; t++) {
        int pa = t & 3;
        __syncthreads();                 // done reading tile t-1 (buffer (t+3)&3)
        stage(t + 3);
        asm volatile("cp.async.wait_group 3;\n");   // tile t arrived
        __syncthreads();

#pragma unroll
        for (int s = 0; s < 2; s++) {
            unsigned af[4][4];
#pragma unroll
            for (int i = 0; i < 4; i++)
                ldsm_x4(af[i], as_sb + (pa * 128 * ASU + (wm0 + 16 * i + lr) * ASU + lkc) * 4 + s * 32);
            unsigned bfr[4][2];
#pragma unroll
            for (int j = 0; j < 4; j++) {
                int col = wn0 + 8 * j + gid;
                bfr[j][0] = Bs[pa * 16 * BSU + (8 * s + tig) * BSU + col];
                bfr[j][1] = Bs[pa * 16 * BSU + (8 * s + tig + 4) * BSU + col];
            }
#pragma unroll
            for (int i = 0; i < 4; i++)
#pragma unroll
                for (int j = 0; j < 4; j++)
                    mma_bf16(acc[i][j], af[i], bfr[j], acc[i][j]);
        }
    }

    float gm = gamma[0];
#pragma unroll
    for (int i = 0; i < 4; i++) {
        int r0 = m0 + wm0 + 16 * i + gid;
#pragma unroll
        for (int j = 0; j < 4; j++) {
            int cc = n0 + wn0 + 8 * j + 2 * tig;
            const float* rr0 = resid + (size_t)b * M * N + (size_t)r0 * N + cc;
            const float* rr1 = rr0 + 8 * N;
            float2 v0 = make_float2(gm * acc[i][j][0] + rr0[0], gm * acc[i][j][1] + rr0[1]);
            float2 v1 = make_float2(gm * acc[i][j][2] + rr1[0], gm * acc[i][j][3] + rr1[1]);
            *(float2*)&C[(size_t)r0 * N + cc]       = v0;
            *(float2*)&C[(size_t)(r0 + 8) * N + cc] = v1;
        }
    }
}

// ---------------- 2x2 maxpool (bf16 in) -> uint4-frag layouts ----------------
__global__ void pool_kernel()
{
    int t = blockIdx.x * blockDim.x + threadIdx.x;
    const int NPHI = BATCH * 32 * MPIX;          // 524288
    if (t < NPHI) {
        int m  = t & 1023;
        int d2 = (t >> 10) & 31;
        int b  = t >> 15;
        int ph = m >> 5, pw = m & 31;
        int n00 = ph * 128 + pw * 2;
        const __nv_bfloat16* r0 = g_Yh + ((size_t)b * 384 + 64 + 2 * d2) * NPIX;
        const __nv_bfloat16* r1 = r0 + NPIX;
        float2 a0 = unpackbf(*(const unsigned*)(r0 + n00));
        float2 a1 = unpackbf(*(const unsigned*)(r0 + n00 + 64));
        float2 c0 = unpackbf(*(const unsigned*)(r1 + n00));
        float2 c1 = unpackbf(*(const unsigned*)(r1 + n00 + 64));
        float v0 = fmaxf(fmaxf(a0.x, a0.y), fmaxf(a1.x, a1.y));
        float v1 = fmaxf(fmaxf(c0.x, c0.y), fmaxf(c1.x, c1.y));
        int s = d2 >> 3, tig = d2 & 3, slot = (d2 >> 2) & 1;
        int sp = s >> 1, se = s & 1, lane = (m & 7) * 4 + tig, mblk = m >> 3;
        g_phq[(((size_t)b * 2 + sp) * 128 + mblk) * 128 + lane * 4 + se * 2 + slot] =
            packbf(v0, v1);
    } else {
        int u = t - NPHI;
        if (u >= BATCH * 512 * 256) return;
        int m2 = u & 511;
        int v  = (u >> 9) & 255;
        int b  = u >> 17;
        int m  = 2 * m2;
        int ph = m >> 5, pw = m & 31;
        int n00 = ph * 128 + pw * 2;
        const __nv_bfloat16* row = g_Yh + ((size_t)b * 384 + 128 + v) * NPIX;
        uint2 w0 = *(const uint2*)(row + n00);
        uint2 w1 = *(const uint2*)(row + n00 + 64);
        float2 p0 = unpackbf(w0.x), p1 = unpackbf(w0.y);
        float2 q0 = unpackbf(w1.x), q1 = unpackbf(w1.y);
        float v0 = fmaxf(fmaxf(p0.x, p0.y), fmaxf(q0.x, q0.y));
        float v1 = fmaxf(fmaxf(p1.x, p1.y), fmaxf(q1.x, q1.y));
        int kk = m2 >> 3, tig = m2 & 3, slot = (m2 >> 2) & 1;
        int vblk = v >> 4, j = (v >> 3) & 1, lane = (v & 7) * 4 + tig;
        g_gq[(((size_t)b * 64 + kk) * 16 + vblk) * 128 + lane * 4 + j * 2 + slot] =
            packbf(v0, v1);
    }
}

// ---------------- fused attention: fused row-max in phase 1 ----------------
// smem (u32): S32[32][516] | ts[32][36] | sinv[32] | pmax[8][32]
#define S32S 516
#define TSS  36
#define ATTN_SMEM ((32 * S32S + 32 * TSS + 32 + 256) * 4)

__global__ void __launch_bounds__(256, 3) attn_kernel()
{
    extern __shared__ unsigned smu[];
    unsigned* S32  = smu;
    unsigned* ts   = smu + 32 * S32S;
    float*    sinv = (float*)(ts + 32 * TSS);
    float*    pmax = sinv + 32;           // [warp][row]

    int b    = blockIdx.y;
    int n0g  = blockIdx.x * 32;
    int tx   = threadIdx.x;
    int wid  = tx >> 5;
    int lane = tx & 31;
    int gid  = lane >> 2;
    int tig  = lane & 3;
    int lr   = (lane & 7) + ((lane >> 3) & 1) * 8;
    int lkc  = (lane >> 4) * 4;

    unsigned ts_sb  = (unsigned)__cvta_generic_to_shared(ts);
    unsigned s32_sb = (unsigned)__cvta_generic_to_shared(S32);

    // theta tile [n][d2] from bf16 Y (bit-pack, no re-round)
    {
        const __nv_bfloat16* Yb = g_Yh + (size_t)b * 384 * NPIX;
        for (int l = tx; l < 32 * 32; l += 256) {
            int n = l & 31, d2 = l >> 5;
            unsigned lo = *(const unsigned short*)&Yb[(size_t)(2 * d2) * NPIX + n0g + n];
            unsigned hi = *(const unsigned short*)&Yb[(size_t)(2 * d2 + 1) * NPIX + n0g + n];
            ts[n * TSS + d2] = lo | (hi << 16);
        }
    }
    __syncthreads();

    // ---- phase 1: S = theta^T phi; per-thread running row max ----
    {
        const uint4* PH4 = (const uint4*)g_phq + (size_t)b * 8192;
        unsigned a_all[4][2][4];
#pragma unroll
        for (int s = 0; s < 4; s++)
#pragma unroll
            for (int i = 0; i < 2; i++)
                ldsm_x4(a_all[s][i], ts_sb + ((16 * i + lr) * TSS + s * 8 + lkc) * 4);

        float rmax[4] = {-1e30f, -1e30f, -1e30f, -1e30f};

#pragma unroll 2
        for (int mj = 0; mj < 16; mj++) {
            int mblk = wid * 16 + mj;
            uint4 Q0 = PH4[(size_t)mblk * 32 + lane];            // sp=0: s=0,1
            uint4 Q1 = PH4[(size_t)(128 + mblk) * 32 + lane];    // sp=1: s=2,3
            float sa0[4] = {0.f, 0.f, 0.f, 0.f};
            float sa1[4] = {0.f, 0.f, 0.f, 0.f};
            {
                unsigned bfr[2] = {Q0.x, Q0.y};
                mma_bf16(sa0, a_all[0][0], bfr, sa0);
                mma_bf16(sa1, a_all[0][1], bfr, sa1);
            }
            {
                unsigned bfr[2] = {Q0.z, Q0.w};
                mma_bf16(sa0, a_all[1][0], bfr, sa0);
                mma_bf16(sa1, a_all[1][1], bfr, sa1);
            }
            {
                unsigned bfr[2] = {Q1.x, Q1.y};
                mma_bf16(sa0, a_all[2][0], bfr, sa0);
                mma_bf16(sa1, a_all[2][1], bfr, sa1);
            }
            {
                unsigned bfr[2] = {Q1.z, Q1.w};
                mma_bf16(sa0, a_all[3][0], bfr, sa0);
                mma_bf16(sa1, a_all[3][1], bfr, sa1);
            }
            rmax[0] = fmaxf(rmax[0], fmaxf(sa0[0], sa0[1]));
            rmax[1] = fmaxf(rmax[1], fmaxf(sa0[2], sa0[3]));
            rmax[2] = fmaxf(rmax[2], fmaxf(sa1[0], sa1[1]));
            rmax[3] = fmaxf(rmax[3], fmaxf(sa1[2], sa1[3]));

            int cc2 = wid * 64 + 4 * mj + tig;
            S32[gid * S32S + cc2]        = packbf(sa0[0], sa0[1]);
            S32[(gid + 8) * S32S + cc2]  = packbf(sa0[2], sa0[3]);
            S32[(gid + 16) * S32S + cc2] = packbf(sa1[0], sa1[1]);
            S32[(gid + 24) * S32S + cc2] = packbf(sa1[2], sa1[3]);
        }
        // reduce over the 4 tig-lanes of each row
#pragma unroll
        for (int q = 0; q < 4; q++) {
            rmax[q] = fmaxf(rmax[q], __shfl_xor_sync(0xFFFFFFFFu, rmax[q], 1));
            rmax[q] = fmaxf(rmax[q], __shfl_xor_sync(0xFFFFFFFFu, rmax[q], 2));
        }
        if (tig == 0) {
            pmax[wid * 32 + gid]      = rmax[0];
            pmax[wid * 32 + gid + 8]  = rmax[1];
            pmax[wid * 32 + gid + 16] = rmax[2];
            pmax[wid * 32 + gid + 24] = rmax[3];
        }
    }
    __syncthreads();

    // ---- phase 2: softmax exp pass (max pre-computed) ----
    {
        for (int rr = wid * 4; rr < wid * 4 + 4; rr++) {
            unsigned* row = S32 + rr * S32S;
            float mx = -1e30f;
#pragma unroll
            for (int w = 0; w < 8; w++) mx = fmaxf(mx, pmax[w * 32 + rr]);
            float sum = 0.f;
            for (int i = lane; i < 512; i += 32) {
                float2 v = unpackbf(row[i]);
                float e0 = __expf(v.x - mx);
                float e1 = __expf(v.y - mx);
                sum += e0 + e1;
                row[i] = packbf(e0, e1);
            }
#pragma unroll
            for (int off = 16; off; off >>= 1)
                sum += __shfl_xor_sync(0xFFFFFFFFu, sum, off);
            if (lane == 0) sinv[rr] = 1.f / sum;
        }
    }
    __syncthreads();

    // ---- phase 3: O = P @ g; warp wid owns v-range [wid*32, wid*32+32) ----
    {
        const uint4* G4 = (const uint4*)g_gq + (size_t)b * 32768;
        int wv0 = wid * 32;
        float acc3[2][4][4];
#pragma unroll
        for (int i = 0; i < 2; i++)
#pragma unroll
            for (int j = 0; j < 4; j++)
#pragma unroll
                for (int q = 0; q < 4; q++) acc3[i][j][q] = 0.f;

        unsigned a_addr0 = s32_sb + (lr * S32S + lkc) * 4;
        unsigned a_addr1 = s32_sb + ((16 + lr) * S32S + lkc) * 4;

#pragma unroll 4
        for (int kk = 0; kk < 64; kk++) {
            uint4 Q0 = G4[(size_t)kk * 512 + (wid * 2) * 32 + lane];      // j=0,1
            uint4 Q1 = G4[(size_t)kk * 512 + (wid * 2 + 1) * 32 + lane];  // j=2,3
            unsigned af0[4], af1[4];
            ldsm_x4(af0, a_addr0 + kk * 32);
            ldsm_x4(af1, a_addr1 + kk * 32);
            {
                unsigned bfr[2] = {Q0.x, Q0.y};
                mma_bf16(acc3[0][0], af0, bfr, acc3[0][0]);
                mma_bf16(acc3[1][0], af1, bfr, acc3[1][0]);
            }
            {
                unsigned bfr[2] = {Q0.z, Q0.w};
                mma_bf16(acc3[0][1], af0, bfr, acc3[0][1]);
                mma_bf16(acc3[1][1], af1, bfr, acc3[1][1]);
            }
            {
                unsigned bfr[2] = {Q1.x, Q1.y};
                mma_bf16(acc3[0][2], af0, bfr, acc3[0][2]);
                mma_bf16(acc3[1][2], af1, bfr, acc3[1][2]);
            }
            {
                unsigned bfr[2] = {Q1.z, Q1.w};
                mma_bf16(acc3[0][3], af0, bfr, acc3[0][3]);
                mma_bf16(acc3[1][3], af1, bfr, acc3[1][3]);
            }
        }
        __syncthreads();   // all warps done reading S32

        // stage O^T (fp32, stride 36) scaled by 1/sum
        float* St = (float*)S32;
#pragma unroll
        for (int i = 0; i < 2; i++) {
            int nn = 16 * i + gid;
            float s0 = sinv[nn];
            float s1 = sinv[nn + 8];
#pragma unroll
            for (int j = 0; j < 4; j++) {
                int vv = wv0 + 8 * j + 2 * tig;
                St[vv * 36 + nn]           = acc3[i][j][0] * s0;
                St[(vv + 1) * 36 + nn]     = acc3[i][j][1] * s0;
                St[vv * 36 + nn + 8]       = acc3[i][j][2] * s1;
                St[(vv + 1) * 36 + nn + 8] = acc3[i][j][3] * s1;
            }
        }
        __syncthreads();

        // packed bf16x2 output [b][v2][n]
        unsigned* ob = g_Ob + (size_t)b * 128 * NPIX;
        for (int it = 0; it < 16; it++) {
            int v2 = wid + 8 * it;
            ob[(size_t)v2 * NPIX + n0g + lane] =
                packbf(St[(2 * v2) * 36 + lane], St[(2 * v2 + 1) * 36 + lane]);
        }
    }
}

// ---------------- launch ----------------
extern "C" void kernel_launch(void* const* d_in, const int* in_sizes, int n_in,
                              void* d_out, int out_size)
{
    const float* x      = (const float*)d_in[0];
    const float* wtheta = (const float*)d_in[1];
    const float* wphi   = (const float*)d_in[2];
    const float* wg     = (const float*)d_in[3];
    const float* wo     = (const float*)d_in[4];
    const float* gamma  = (const float*)d_in[5];
    float* out = (float*)d_out;

    unsigned *dWb, *dWob, *dOb;
    __nv_bfloat16* dYh;
    cudaGetSymbolAddress((void**)&dWb,  g_Wb);
    cudaGetSymbolAddress((void**)&dWob, g_Wob);
    cudaGetSymbolAddress((void**)&dYh,  g_Yh);
    cudaGetSymbolAddress((void**)&dOb,  g_Ob);

    cudaFuncSetAttribute(attn_kernel,
                         cudaFuncAttributeMaxDynamicSharedMemorySize, ATTN_SMEM);
    cudaFuncSetAttribute(gemm_proj,
                         cudaFuncAttributeMaxDynamicSharedMemorySize, PROJ_SMEM);
    cudaFuncSetAttribute(gemm_async,
                         cudaFuncAttributeMaxDynamicSharedMemorySize, GASY_SMEM);

    // 1) weights -> bf16 pairs
    wcvt_kernel<<<(384 * 256 + 512 * 128 + 255) / 256, 256>>>(wtheta, wphi, wg, wo);

    // 2) projections: Yh[b] = bf16(Wcat @ x[b])
    {
        dim3 grid(NPIX / 128, 384 / 128, BATCH);
        gemm_proj<<<grid, 256, PROJ_SMEM>>>(dWb, x, dYh, 384, 256, NPIX);
    }

    // 3) 2x2 maxpool -> uint4-frag phi, g
    {
        int total = BATCH * 32 * MPIX + BATCH * 512 * 256;
        pool_kernel<<<(total + 255) / 256, 256>>>();
    }

    // 4) fused attention -> packed o
    {
        dim3 grid(NPIX / 32, BATCH);
        attn_kernel<<<grid, 256, ATTN_SMEM>>>();
    }

    // 5) out = gamma * (w_o @ o) + x   (M=512, K2=128, N=4096)
    {
        dim3 grid(NPIX / 128, 512 / 128, BATCH);
        gemm_async<<<grid, 256, GASY_SMEM>>>(dWob, dOb, out, 512, 128, NPIX, gamma, x);
    }
}

// round 13
// speedup vs baseline: 1.1641x; 1.1641x over previous
#include <cuda_runtime.h>
#include <cuda_bf16.h>

#define BATCH 16
#define NPIX  4096   // 64*64
#define MPIX  1024   // 32*32

// ---------------- scratch (device globals; no allocation) ----------------
__device__ unsigned g_Wb[384 * 256];                            // [theta;phi;g] bf16x2 k-pairs
__device__ unsigned g_Wob[512 * 128];                           // w_o bf16x2 k-pairs
__device__ __nv_bfloat16 g_Yh[(size_t)BATCH * 384 * NPIX];      // projections bf16
__device__ __align__(16) unsigned g_phq[(size_t)BATCH * 32768]; // phi, uint4-frag layout
__device__ __align__(16) unsigned g_gq[(size_t)BATCH * 131072]; // g,   uint4-frag layout
__device__ unsigned g_Ob[(size_t)BATCH * 128 * NPIX];           // attn out bf16x2 [b][v2][n]

// ---------------- helpers ----------------
__device__ __forceinline__ unsigned packbf(float lo, float hi) {
    __nv_bfloat162 h = __floats2bfloat162_rn(lo, hi);
    return *(unsigned*)&h;
}
__device__ __forceinline__ float2 unpackbf(unsigned u) {
    __nv_bfloat162 h = *(__nv_bfloat162*)&u;
    return __bfloat1622float2(h);
}
__device__ __forceinline__ void mma_bf16(float* d, const unsigned* a, const unsigned* b,
                                         const float* c)
{
    asm volatile(
        "mma.sync.aligned.m16n8k16.row.col.f32.bf16.bf16.f32 "
        "{%0,%1,%2,%3}, {%4,%5,%6,%7}, {%8,%9}, {%10,%11,%12,%13};\n"
        : "=f"(d[0]), "=f"(d[1]), "=f"(d[2]), "=f"(d[3])
        : "r"(a[0]), "r"(a[1]), "r"(a[2]), "r"(a[3]),
          "r"(b[0]), "r"(b[1]),
          "f"(c[0]), "f"(c[1]), "f"(c[2]), "f"(c[3]));
}
__device__ __forceinline__ void ldsm_x4(unsigned* r, unsigned saddr) {
    asm volatile(
        "ldmatrix.sync.aligned.m8n8.x4.shared.b16 {%0,%1,%2,%3}, [%4];"
        : "=r"(r[0]), "=r"(r[1]), "=r"(r[2]), "=r"(r[3]) : "r"(saddr));
}
#define CP16(dst, src) \
    asm volatile("cp.async.cg.shared.global [%0], [%1], 16;\n" :: "r"(dst), "l"(src))

// ---------------- weight convert/concat -> bf16 pairs ----------------
__global__ void wcvt_kernel(const float* __restrict__ wt, const float* __restrict__ wp,
                            const float* __restrict__ wg, const float* __restrict__ wo)
{
    int t = blockIdx.x * blockDim.x + threadIdx.x;
    if (t < 384 * 256) {
        int row = t >> 8, k2 = t & 255;
        const float* src;
        if (row < 64)       src = wt + (size_t)row * 512;
        else if (row < 128) src = wp + (size_t)(row - 64) * 512;
        else                src = wg + (size_t)(row - 128) * 512;
        g_Wb[t] = packbf(src[2 * k2], src[2 * k2 + 1]);
    } else {
        int u = t - 384 * 256;
        if (u >= 512 * 128) return;
        int row = u >> 7, k2 = u & 127;
        g_Wob[u] = packbf(wo[(size_t)row * 256 + 2 * k2], wo[(size_t)row * 256 + 2 * k2 + 1]);
    }
}

#define ASU 20
#define BSU 136

// ---------------- projection GEMM: A bf16-pairs, B fp32 (convert in staging) ----
// Yh[b] = bf16(Wcat @ x[b]);  M=384, K2=256, N=4096
__global__ void __launch_bounds__(256, 2) gemm_proj(
    const unsigned* __restrict__ A, const float* __restrict__ Xbase,
    __nv_bfloat16* __restrict__ Cbase, int M, int K2, int N)
{
    int b = blockIdx.z;
    const float* X = Xbase + (size_t)b * (2 * K2) * N;
    __nv_bfloat16* C = Cbase + (size_t)b * M * N;
    int m0 = blockIdx.y * 128;
    int n0 = blockIdx.x * 128;

    __shared__ unsigned As[2][128 * ASU];
    __shared__ unsigned Bs[2][16 * BSU];

    int tx   = threadIdx.x;
    int wid  = tx >> 5;
    int lane = tx & 31;
    int gid  = lane >> 2;
    int tig  = lane & 3;
    int wm0  = (wid & 1) * 64;
    int wn0  = (wid >> 1) * 32;
    int lr   = (lane & 7) + ((lane >> 3) & 1) * 8;
    int lkc  = (lane >> 4) * 4;

    unsigned asb[2], bsb[2];
    asb[0] = (unsigned)__cvta_generic_to_shared(&As[0][0]);
    asb[1] = (unsigned)__cvta_generic_to_shared(&As[1][0]);
    bsb[0] = (unsigned)__cvta_generic_to_shared(&Bs[0][0]);
    bsb[1] = (unsigned)__cvta_generic_to_shared(&Bs[1][0]);

    int bkr[2], bn4[2];
#pragma unroll
    for (int r = 0; r < 2; r++) {
        int idx = tx + 256 * r;
        bkr[r] = idx >> 5;
        bn4[r] = (idx & 31) * 4;
    }

    float acc[4][4][4];
#pragma unroll
    for (int i = 0; i < 4; i++)
#pragma unroll
        for (int j = 0; j < 4; j++)
#pragma unroll
            for (int q = 0; q < 4; q++) acc[i][j][q] = 0.f;

    auto stageA = [&](int k02, int p) {
#pragma unroll
        for (int r = 0; r < 2; r++) {
            int idx = tx + 256 * r;
            int am = idx >> 2, c4 = (idx & 3) * 4;
            CP16(asb[p] + (am * ASU + c4) * 4,
                 (const void*)&A[(size_t)(m0 + am) * K2 + k02 + c4]);
        }
        asm volatile("cp.async.commit_group;\n");
    };
    auto ldgB = [&](int k02, float4* r0v, float4* r1v) {
#pragma unroll
        for (int r = 0; r < 2; r++) {
            const float* p0 = &X[(size_t)(2 * (k02 + bkr[r])) * N + n0 + bn4[r]];
            r0v[r] = *(const float4*)p0;
            r1v[r] = *(const float4*)(p0 + N);
        }
    };

    float4 b0[2], b1[2];
    ldgB(0, b0, b1);
    stageA(0, 0);
    int p = 0;
    for (int k02 = 0; k02 < K2; k02 += 16) {
        __syncthreads();
#pragma unroll
        for (int r = 0; r < 2; r++) {
            uint4 pv = make_uint4(packbf(b0[r].x, b1[r].x), packbf(b0[r].y, b1[r].y),
                                  packbf(b0[r].z, b1[r].z), packbf(b0[r].w, b1[r].w));
            *(uint4*)&Bs[p][bkr[r] * BSU + bn4[r]] = pv;
        }
        bool nxt = (k02 + 16 < K2);
        if (nxt) {
            ldgB(k02 + 16, b0, b1);
            stageA(k02 + 16, p ^ 1);
            asm volatile("cp.async.wait_group 1;\n");
        } else {
            asm volatile("cp.async.wait_group 0;\n");
        }
        __syncthreads();

#pragma unroll
        for (int s = 0; s < 2; s++) {
            unsigned af[4][4];
#pragma unroll
            for (int i = 0; i < 4; i++)
                ldsm_x4(af[i], asb[p] + ((wm0 + 16 * i + lr) * ASU + lkc) * 4 + s * 32);
            unsigned bfr[4][2];
#pragma unroll
            for (int j = 0; j < 4; j++) {
                int col = wn0 + 8 * j + gid;
                bfr[j][0] = Bs[p][(8 * s + tig) * BSU + col];
                bfr[j][1] = Bs[p][(8 * s + tig + 4) * BSU + col];
            }
#pragma unroll
            for (int i = 0; i < 4; i++)
#pragma unroll
                for (int j = 0; j < 4; j++)
                    mma_bf16(acc[i][j], af[i], bfr[j], acc[i][j]);
        }
        p ^= 1;
    }

    // epilogue: write bf16 pairs (cc, cc+1) along n
#pragma unroll
    for (int i = 0; i < 4; i++) {
        int r0 = m0 + wm0 + 16 * i + gid;
#pragma unroll
        for (int j = 0; j < 4; j++) {
            int cc = n0 + wn0 + 8 * j + 2 * tig;
            *(unsigned*)&C[(size_t)r0 * N + cc]       = packbf(acc[i][j][0], acc[i][j][1]);
            *(unsigned*)&C[(size_t)(r0 + 8) * N + cc] = packbf(acc[i][j][2], acc[i][j][3]);
        }
    }
}

// ---------------- final GEMM: both operands bf16-packed, cp.async 2-stage ------
__global__ void __launch_bounds__(256, 2) gemm_async(
    const unsigned* __restrict__ A, const unsigned* __restrict__ Bbase,
    float* __restrict__ Cbase,
    int M, int K2, int N,
    const float* __restrict__ gamma, const float* __restrict__ resid)
{
    int b = blockIdx.z;
    const unsigned* B = Bbase + (size_t)b * K2 * N;
    float* C = Cbase + (size_t)b * M * N;
    int m0 = blockIdx.y * 128;
    int n0 = blockIdx.x * 128;

    __shared__ unsigned As[2][128 * ASU];
    __shared__ unsigned Bs[2][16 * BSU];

    int tx   = threadIdx.x;
    int wid  = tx >> 5;
    int lane = tx & 31;
    int gid  = lane >> 2;
    int tig  = lane & 3;
    int wm0  = (wid & 1) * 64;
    int wn0  = (wid >> 1) * 32;
    int lr   = (lane & 7) + ((lane >> 3) & 1) * 8;
    int lkc  = (lane >> 4) * 4;

    unsigned asb[2], bsb[2];
    asb[0] = (unsigned)__cvta_generic_to_shared(&As[0][0]);
    asb[1] = (unsigned)__cvta_generic_to_shared(&As[1][0]);
    bsb[0] = (unsigned)__cvta_generic_to_shared(&Bs[0][0]);
    bsb[1] = (unsigned)__cvta_generic_to_shared(&Bs[1][0]);

    float acc[4][4][4];
#pragma unroll
    for (int i = 0; i < 4; i++)
#pragma unroll
        for (int j = 0; j < 4; j++)
#pragma unroll
            for (int q = 0; q < 4; q++) acc[i][j][q] = 0.f;

    auto stage = [&](int k02, int p) {
#pragma unroll
        for (int r = 0; r < 2; r++) {
            int idx = tx + 256 * r;
            int am = idx >> 2, c4 = (idx & 3) * 4;
            CP16(asb[p] + (am * ASU + c4) * 4,
                 (const void*)&A[(size_t)(m0 + am) * K2 + k02 + c4]);
            int kr = idx >> 5, n4 = (idx & 31) * 4;
            CP16(bsb[p] + (kr * BSU + n4) * 4,
                 (const void*)&B[(size_t)(k02 + kr) * N + n0 + n4]);
        }
        asm volatile("cp.async.commit_group;\n");
    };

    stage(0, 0);
    int p = 0;
    for (int k02 = 0; k02 < K2; k02 += 16) {
        __syncthreads();
        bool nxt = (k02 + 16 < K2);
        if (nxt) {
            stage(k02 + 16, p ^ 1);
            asm volatile("cp.async.wait_group 1;\n");
        } else {
            asm volatile("cp.async.wait_group 0;\n");
        }
        __syncthreads();

#pragma unroll
        for (int s = 0; s < 2; s++) {
            unsigned af[4][4];
#pragma unroll
            for (int i = 0; i < 4; i++)
                ldsm_x4(af[i], asb[p] + ((wm0 + 16 * i + lr) * ASU + lkc) * 4 + s * 32);
            unsigned bfr[4][2];
#pragma unroll
            for (int j = 0; j < 4; j++) {
                int col = wn0 + 8 * j + gid;
                bfr[j][0] = Bs[p][(8 * s + tig) * BSU + col];
                bfr[j][1] = Bs[p][(8 * s + tig + 4) * BSU + col];
            }
#pragma unroll
            for (int i = 0; i < 4; i++)
#pragma unroll
                for (int j = 0; j < 4; j++)
                    mma_bf16(acc[i][j], af[i], bfr[j], acc[i][j]);
        }
        p ^= 1;
    }

    float gm = gamma[0];
#pragma unroll
    for (int i = 0; i < 4; i++) {
        int r0 = m0 + wm0 + 16 * i + gid;
#pragma unroll
        for (int j = 0; j < 4; j++) {
            int cc = n0 + wn0 + 8 * j + 2 * tig;
            const float* rr0 = resid + (size_t)b * M * N + (size_t)r0 * N + cc;
            const float* rr1 = rr0 + 8 * N;
            float2 v0 = make_float2(gm * acc[i][j][0] + rr0[0], gm * acc[i][j][1] + rr0[1]);
            float2 v1 = make_float2(gm * acc[i][j][2] + rr1[0], gm * acc[i][j][3] + rr1[1]);
            *(float2*)&C[(size_t)r0 * N + cc]       = v0;
            *(float2*)&C[(size_t)(r0 + 8) * N + cc] = v1;
        }
    }
}

// ---------------- 2x2 maxpool (bf16 in) -> uint4-frag layouts ----------------
__global__ void pool_kernel()
{
    int t = blockIdx.x * blockDim.x + threadIdx.x;
    const int NPHI = BATCH * 32 * MPIX;          // 524288
    if (t < NPHI) {
        int m  = t & 1023;
        int d2 = (t >> 10) & 31;
        int b  = t >> 15;
        int ph = m >> 5, pw = m & 31;
        int n00 = ph * 128 + pw * 2;
        const __nv_bfloat16* r0 = g_Yh + ((size_t)b * 384 + 64 + 2 * d2) * NPIX;
        const __nv_bfloat16* r1 = r0 + NPIX;
        float2 a0 = unpackbf(*(const unsigned*)(r0 + n00));
        float2 a1 = unpackbf(*(const unsigned*)(r0 + n00 + 64));
        float2 c0 = unpackbf(*(const unsigned*)(r1 + n00));
        float2 c1 = unpackbf(*(const unsigned*)(r1 + n00 + 64));
        float v0 = fmaxf(fmaxf(a0.x, a0.y), fmaxf(a1.x, a1.y));
        float v1 = fmaxf(fmaxf(c0.x, c0.y), fmaxf(c1.x, c1.y));
        int s = d2 >> 3, tig = d2 & 3, slot = (d2 >> 2) & 1;
        int sp = s >> 1, se = s & 1, lane = (m & 7) * 4 + tig, mblk = m >> 3;
        g_phq[(((size_t)b * 2 + sp) * 128 + mblk) * 128 + lane * 4 + se * 2 + slot] =
            packbf(v0, v1);
    } else {
        int u = t - NPHI;
        if (u >= BATCH * 512 * 256) return;
        int m2 = u & 511;
        int v  = (u >> 9) & 255;
        int b  = u >> 17;
        int m  = 2 * m2;
        int ph = m >> 5, pw = m & 31;
        int n00 = ph * 128 + pw * 2;
        const __nv_bfloat16* row = g_Yh + ((size_t)b * 384 + 128 + v) * NPIX;
        uint2 w0 = *(const uint2*)(row + n00);
        uint2 w1 = *(const uint2*)(row + n00 + 64);
        float2 p0 = unpackbf(w0.x), p1 = unpackbf(w0.y);
        float2 q0 = unpackbf(w1.x), q1 = unpackbf(w1.y);
        float v0 = fmaxf(fmaxf(p0.x, p0.y), fmaxf(q0.x, q0.y));
        float v1 = fmaxf(fmaxf(p1.x, p1.y), fmaxf(q1.x, q1.y));
        int kk = m2 >> 3, tig = m2 & 3, slot = (m2 >> 2) & 1;
        int vblk = v >> 4, j = (v >> 3) & 1, lane = (v & 7) * 4 + tig;
        g_gq[(((size_t)b * 64 + kk) * 16 + vblk) * 128 + lane * 4 + j * 2 + slot] =
            packbf(v0, v1);
    }
}

// ---------------- fused attention: fused row-max in phase 1 ----------------
// smem (u32): S32[32][516] | ts[32][36] | sinv[32] | pmax[8][32]
#define S32S 516
#define TSS  36
#define ATTN_SMEM ((32 * S32S + 32 * TSS + 32 + 256) * 4)

__global__ void __launch_bounds__(256, 3) attn_kernel()
{
    extern __shared__ unsigned smu[];
    unsigned* S32  = smu;
    unsigned* ts   = smu + 32 * S32S;
    float*    sinv = (float*)(ts + 32 * TSS);
    float*    pmax = sinv + 32;           // [warp][row]

    int b    = blockIdx.y;
    int n0g  = blockIdx.x * 32;
    int tx   = threadIdx.x;
    int wid  = tx >> 5;
    int lane = tx & 31;
    int gid  = lane >> 2;
    int tig  = lane & 3;
    int lr   = (lane & 7) + ((lane >> 3) & 1) * 8;
    int lkc  = (lane >> 4) * 4;

    unsigned ts_sb  = (unsigned)__cvta_generic_to_shared(ts);
    unsigned s32_sb = (unsigned)__cvta_generic_to_shared(S32);

    // theta tile [n][d2] from bf16 Y (bit-pack, no re-round)
    {
        const __nv_bfloat16* Yb = g_Yh + (size_t)b * 384 * NPIX;
        for (int l = tx; l < 32 * 32; l += 256) {
            int n = l & 31, d2 = l >> 5;
            unsigned lo = *(const unsigned short*)&Yb[(size_t)(2 * d2) * NPIX + n0g + n];
            unsigned hi = *(const unsigned short*)&Yb[(size_t)(2 * d2 + 1) * NPIX + n0g + n];
            ts[n * TSS + d2] = lo | (hi << 16);
        }
    }
    __syncthreads();

    // ---- phase 1: S = theta^T phi; per-thread running row max ----
    {
        const uint4* PH4 = (const uint4*)g_phq + (size_t)b * 8192;
        unsigned a_all[4][2][4];
#pragma unroll
        for (int s = 0; s < 4; s++)
#pragma unroll
            for (int i = 0; i < 2; i++)
                ldsm_x4(a_all[s][i], ts_sb + ((16 * i + lr) * TSS + s * 8 + lkc) * 4);

        float rmax[4] = {-1e30f, -1e30f, -1e30f, -1e30f};

#pragma unroll 2
        for (int mj = 0; mj < 16; mj++) {
            int mblk = wid * 16 + mj;
            uint4 Q0 = PH4[(size_t)mblk * 32 + lane];            // sp=0: s=0,1
            uint4 Q1 = PH4[(size_t)(128 + mblk) * 32 + lane];    // sp=1: s=2,3
            float sa0[4] = {0.f, 0.f, 0.f, 0.f};
            float sa1[4] = {0.f, 0.f, 0.f, 0.f};
            {
                unsigned bfr[2] = {Q0.x, Q0.y};
                mma_bf16(sa0, a_all[0][0], bfr, sa0);
                mma_bf16(sa1, a_all[0][1], bfr, sa1);
            }
            {
                unsigned bfr[2] = {Q0.z, Q0.w};
                mma_bf16(sa0, a_all[1][0], bfr, sa0);
                mma_bf16(sa1, a_all[1][1], bfr, sa1);
            }
            {
                unsigned bfr[2] = {Q1.x, Q1.y};
                mma_bf16(sa0, a_all[2][0], bfr, sa0);
                mma_bf16(sa1, a_all[2][1], bfr, sa1);
            }
            {
                unsigned bfr[2] = {Q1.z, Q1.w};
                mma_bf16(sa0, a_all[3][0], bfr, sa0);
                mma_bf16(sa1, a_all[3][1], bfr, sa1);
            }
            rmax[0] = fmaxf(rmax[0], fmaxf(sa0[0], sa0[1]));
            rmax[1] = fmaxf(rmax[1], fmaxf(sa0[2], sa0[3]));
            rmax[2] = fmaxf(rmax[2], fmaxf(sa1[0], sa1[1]));
            rmax[3] = fmaxf(rmax[3], fmaxf(sa1[2], sa1[3]));

            int cc2 = wid * 64 + 4 * mj + tig;
            S32[gid * S32S + cc2]        = packbf(sa0[0], sa0[1]);
            S32[(gid + 8) * S32S + cc2]  = packbf(sa0[2], sa0[3]);
            S32[(gid + 16) * S32S + cc2] = packbf(sa1[0], sa1[1]);
            S32[(gid + 24) * S32S + cc2] = packbf(sa1[2], sa1[3]);
        }
        // reduce over the 4 tig-lanes of each row
#pragma unroll
        for (int q = 0; q < 4; q++) {
            rmax[q] = fmaxf(rmax[q], __shfl_xor_sync(0xFFFFFFFFu, rmax[q], 1));
            rmax[q] = fmaxf(rmax[q], __shfl_xor_sync(0xFFFFFFFFu, rmax[q], 2));
        }
        if (tig == 0) {
            pmax[wid * 32 + gid]      = rmax[0];
            pmax[wid * 32 + gid + 8]  = rmax[1];
            pmax[wid * 32 + gid + 16] = rmax[2];
            pmax[wid * 32 + gid + 24] = rmax[3];
        }
    }
    __syncthreads();

    // ---- phase 2: softmax exp pass (max pre-computed) ----
    {
        for (int rr = wid * 4; rr < wid * 4 + 4; rr++) {
            unsigned* row = S32 + rr * S32S;
            float mx = -1e30f;
#pragma unroll
            for (int w = 0; w < 8; w++) mx = fmaxf(mx, pmax[w * 32 + rr]);
            float sum = 0.f;
            for (int i = lane; i < 512; i += 32) {
                float2 v = unpackbf(row[i]);
                float e0 = __expf(v.x - mx);
                float e1 = __expf(v.y - mx);
                sum += e0 + e1;
                row[i] = packbf(e0, e1);
            }
#pragma unroll
            for (int off = 16; off; off >>= 1)
                sum += __shfl_xor_sync(0xFFFFFFFFu, sum, off);
            if (lane == 0) sinv[rr] = 1.f / sum;
        }
    }
    __syncthreads();

    // ---- phase 3: O = P @ g; warp wid owns v-range [wid*32, wid*32+32) ----
    {
        const uint4* G4 = (const uint4*)g_gq + (size_t)b * 32768;
        int wv0 = wid * 32;
        float acc3[2][4][4];
#pragma unroll
        for (int i = 0; i < 2; i++)
#pragma unroll
            for (int j = 0; j < 4; j++)
#pragma unroll
                for (int q = 0; q < 4; q++) acc3[i][j][q] = 0.f;

        unsigned a_addr0 = s32_sb + (lr * S32S + lkc) * 4;
        unsigned a_addr1 = s32_sb + ((16 + lr) * S32S + lkc) * 4;

#pragma unroll 4
        for (int kk = 0; kk < 64; kk++) {
            uint4 Q0 = G4[(size_t)kk * 512 + (wid * 2) * 32 + lane];      // j=0,1
            uint4 Q1 = G4[(size_t)kk * 512 + (wid * 2 + 1) * 32 + lane];  // j=2,3
            unsigned af0[4], af1[4];
            ldsm_x4(af0, a_addr0 + kk * 32);
            ldsm_x4(af1, a_addr1 + kk * 32);
            {
                unsigned bfr[2] = {Q0.x, Q0.y};
                mma_bf16(acc3[0][0], af0, bfr, acc3[0][0]);
                mma_bf16(acc3[1][0], af1, bfr, acc3[1][0]);
            }
            {
                unsigned bfr[2] = {Q0.z, Q0.w};
                mma_bf16(acc3[0][1], af0, bfr, acc3[0][1]);
                mma_bf16(acc3[1][1], af1, bfr, acc3[1][1]);
            }
            {
                unsigned bfr[2] = {Q1.x, Q1.y};
                mma_bf16(acc3[0][2], af0, bfr, acc3[0][2]);
                mma_bf16(acc3[1][2], af1, bfr, acc3[1][2]);
            }
            {
                unsigned bfr[2] = {Q1.z, Q1.w};
                mma_bf16(acc3[0][3], af0, bfr, acc3[0][3]);
                mma_bf16(acc3[1][3], af1, bfr, acc3[1][3]);
            }
        }
        __syncthreads();   // all warps done reading S32

        // stage O^T (fp32, stride 36) scaled by 1/sum
        float* St = (float*)S32;
#pragma unroll
        for (int i = 0; i < 2; i++) {
            int nn = 16 * i + gid;
            float s0 = sinv[nn];
            float s1 = sinv[nn + 8];
#pragma unroll
            for (int j = 0; j < 4; j++) {
                int vv = wv0 + 8 * j + 2 * tig;
                St[vv * 36 + nn]           = acc3[i][j][0] * s0;
                St[(vv + 1) * 36 + nn]     = acc3[i][j][1] * s0;
                St[vv * 36 + nn + 8]       = acc3[i][j][2] * s1;
                St[(vv + 1) * 36 + nn + 8] = acc3[i][j][3] * s1;
            }
        }
        __syncthreads();

        // packed bf16x2 output [b][v2][n]
        unsigned* ob = g_Ob + (size_t)b * 128 * NPIX;
        for (int it = 0; it < 16; it++) {
            int v2 = wid + 8 * it;
            ob[(size_t)v2 * NPIX + n0g + lane] =
                packbf(St[(2 * v2) * 36 + lane], St[(2 * v2 + 1) * 36 + lane]);
        }
    }
}

// ---------------- launch ----------------
extern "C" void kernel_launch(void* const* d_in, const int* in_sizes, int n_in,
                              void* d_out, int out_size)
{
    const float* x      = (const float*)d_in[0];
    const float* wtheta = (const float*)d_in[1];
    const float* wphi   = (const float*)d_in[2];
    const float* wg     = (const float*)d_in[3];
    const float* wo     = (const float*)d_in[4];
    const float* gamma  = (const float*)d_in[5];
    float* out = (float*)d_out;

    unsigned *dWb, *dWob, *dOb;
    __nv_bfloat16* dYh;
    cudaGetSymbolAddress((void**)&dWb,  g_Wb);
    cudaGetSymbolAddress((void**)&dWob, g_Wob);
    cudaGetSymbolAddress((void**)&dYh,  g_Yh);
    cudaGetSymbolAddress((void**)&dOb,  g_Ob);

    cudaFuncSetAttribute(attn_kernel,
                         cudaFuncAttributeMaxDynamicSharedMemorySize, ATTN_SMEM);

    // 1) weights -> bf16 pairs
    wcvt_kernel<<<(384 * 256 + 512 * 128 + 255) / 256, 256>>>(wtheta, wphi, wg, wo);

    // 2) projections: Yh[b] = bf16(Wcat @ x[b])
    {
        dim3 grid(NPIX / 128, 384 / 128, BATCH);
        gemm_proj<<<grid, 256>>>(dWb, x, dYh, 384, 256, NPIX);
    }

    // 3) 2x2 maxpool -> uint4-frag phi, g
    {
        int total = BATCH * 32 * MPIX + BATCH * 512 * 256;
        pool_kernel<<<(total + 255) / 256, 256>>>();
    }

    // 4) fused attention -> packed o
    {
        dim3 grid(NPIX / 32, BATCH);
        attn_kernel<<<grid, 256, ATTN_SMEM>>>();
    }

    // 5) out = gamma * (w_o @ o) + x   (M=512, K2=128, N=4096)
    {
        dim3 grid(NPIX / 128, 512 / 128, BATCH);
        gemm_async<<<grid, 256>>>(dWob, dOb, out, 512, 128, NPIX, gamma, x);
    }
}

// round 14
// speedup vs baseline: 1.1748x; 1.0092x over previous
#include <cuda_runtime.h>
#include <cuda_bf16.h>

#define BATCH 16
#define NPIX  4096   // 64*64
#define MPIX  1024   // 32*32

// ---------------- scratch (device globals; no allocation) ----------------
__device__ unsigned g_Wb[384 * 256];                            // [theta;phi;g] bf16x2 k-pairs
__device__ unsigned g_Wob[512 * 128];                           // w_o bf16x2 k-pairs
__device__ __nv_bfloat16 g_Yh[(size_t)BATCH * 384 * NPIX];      // theta rows (bf16)
__device__ __align__(16) unsigned g_phq[(size_t)BATCH * 32768]; // phi, uint4-frag layout
__device__ __align__(16) unsigned g_gq[(size_t)BATCH * 131072]; // g,   uint4-frag layout
__device__ unsigned g_Ob[(size_t)BATCH * 128 * NPIX];           // attn out bf16x2 [b][v2][n]

// ---------------- helpers ----------------
__device__ __forceinline__ unsigned packbf(float lo, float hi) {
    __nv_bfloat162 h = __floats2bfloat162_rn(lo, hi);
    return *(unsigned*)&h;
}
__device__ __forceinline__ float2 unpackbf(unsigned u) {
    __nv_bfloat162 h = *(__nv_bfloat162*)&u;
    return __bfloat1622float2(h);
}
__device__ __forceinline__ void mma_bf16(float* d, const unsigned* a, const unsigned* b,
                                         const float* c)
{
    asm volatile(
        "mma.sync.aligned.m16n8k16.row.col.f32.bf16.bf16.f32 "
        "{%0,%1,%2,%3}, {%4,%5,%6,%7}, {%8,%9}, {%10,%11,%12,%13};\n"
        : "=f"(d[0]), "=f"(d[1]), "=f"(d[2]), "=f"(d[3])
        : "r"(a[0]), "r"(a[1]), "r"(a[2]), "r"(a[3]),
          "r"(b[0]), "r"(b[1]),
          "f"(c[0]), "f"(c[1]), "f"(c[2]), "f"(c[3]));
}
__device__ __forceinline__ void ldsm_x4(unsigned* r, unsigned saddr) {
    asm volatile(
        "ldmatrix.sync.aligned.m8n8.x4.shared.b16 {%0,%1,%2,%3}, [%4];"
        : "=r"(r[0]), "=r"(r[1]), "=r"(r[2]), "=r"(r[3]) : "r"(saddr));
}
#define CP16(dst, src) \
    asm volatile("cp.async.cg.shared.global [%0], [%1], 16;\n" :: "r"(dst), "l"(src))

// ---------------- weight convert/concat -> bf16 pairs ----------------
__global__ void wcvt_kernel(const float* __restrict__ wt, const float* __restrict__ wp,
                            const float* __restrict__ wg, const float* __restrict__ wo)
{
    int t = blockIdx.x * blockDim.x + threadIdx.x;
    if (t < 384 * 256) {
        int row = t >> 8, k2 = t & 255;
        const float* src;
        if (row < 64)       src = wt + (size_t)row * 512;
        else if (row < 128) src = wp + (size_t)(row - 64) * 512;
        else                src = wg + (size_t)(row - 128) * 512;
        g_Wb[t] = packbf(src[2 * k2], src[2 * k2 + 1]);
    } else {
        int u = t - 384 * 256;
        if (u >= 512 * 128) return;
        int row = u >> 7, k2 = u & 127;
        g_Wob[u] = packbf(wo[(size_t)row * 256 + 2 * k2], wo[(size_t)row * 256 + 2 * k2 + 1]);
    }
}

#define ASU 20
#define BSU 136
#define HMS 65   // pooled-staging stride (floats)

// ---------------- projection GEMM + fused 2x2 maxpool epilogue ----------------
// m-tile 0: rows 0-63 theta -> Yh; rows 64-127 phi -> pooled g_phq
// m-tiles 1,2: g channels -> pooled g_gq
__global__ void __launch_bounds__(256, 2) gemm_proj(
    const unsigned* __restrict__ A, const float* __restrict__ Xbase,
    __nv_bfloat16* __restrict__ Cbase, int M, int K2, int N)
{
    // union: [As0|As1|Bs0|Bs1] during mainloop; hm[128][HMS] floats in epilogue
    __shared__ unsigned sbuf[2 * 128 * ASU + 2 * 16 * BSU];   // 37.9 KB >= 33.3 KB
    unsigned* Bsp = sbuf + 2 * 128 * ASU;
    float*    hm  = (float*)sbuf;

    int b = blockIdx.z;
    const float* X = Xbase + (size_t)b * (2 * K2) * N;
    __nv_bfloat16* C = Cbase + (size_t)b * M * N;
    int m0 = blockIdx.y * 128;
    int n0 = blockIdx.x * 128;

    int tx   = threadIdx.x;
    int wid  = tx >> 5;
    int lane = tx & 31;
    int gid  = lane >> 2;
    int tig  = lane & 3;
    int wm0  = (wid & 1) * 64;
    int wn0  = (wid >> 1) * 32;
    int lr   = (lane & 7) + ((lane >> 3) & 1) * 8;
    int lkc  = (lane >> 4) * 4;

    unsigned sb_base = (unsigned)__cvta_generic_to_shared(sbuf);
    unsigned asb[2];
    asb[0] = sb_base;
    asb[1] = sb_base + 128 * ASU * 4;

    int bkr[2], bn4[2];
#pragma unroll
    for (int r = 0; r < 2; r++) {
        int idx = tx + 256 * r;
        bkr[r] = idx >> 5;
        bn4[r] = (idx & 31) * 4;
    }

    float acc[4][4][4];
#pragma unroll
    for (int i = 0; i < 4; i++)
#pragma unroll
        for (int j = 0; j < 4; j++)
#pragma unroll
            for (int q = 0; q < 4; q++) acc[i][j][q] = 0.f;

    auto stageA = [&](int k02, int p) {
#pragma unroll
        for (int r = 0; r < 2; r++) {
            int idx = tx + 256 * r;
            int am = idx >> 2, c4 = (idx & 3) * 4;
            CP16(asb[p] + (am * ASU + c4) * 4,
                 (const void*)&A[(size_t)(m0 + am) * K2 + k02 + c4]);
        }
        asm volatile("cp.async.commit_group;\n");
    };
    auto ldgB = [&](int k02, float4* r0v, float4* r1v) {
#pragma unroll
        for (int r = 0; r < 2; r++) {
            const float* p0 = &X[(size_t)(2 * (k02 + bkr[r])) * N + n0 + bn4[r]];
            r0v[r] = *(const float4*)p0;
            r1v[r] = *(const float4*)(p0 + N);
        }
    };

    float4 b0[2], b1[2];
    ldgB(0, b0, b1);
    stageA(0, 0);
    int p = 0;
    for (int k02 = 0; k02 < K2; k02 += 16) {
        __syncthreads();
#pragma unroll
        for (int r = 0; r < 2; r++) {
            uint4 pv = make_uint4(packbf(b0[r].x, b1[r].x), packbf(b0[r].y, b1[r].y),
                                  packbf(b0[r].z, b1[r].z), packbf(b0[r].w, b1[r].w));
            *(uint4*)&Bsp[p * 16 * BSU + bkr[r] * BSU + bn4[r]] = pv;
        }
        bool nxt = (k02 + 16 < K2);
        if (nxt) {
            ldgB(k02 + 16, b0, b1);
            stageA(k02 + 16, p ^ 1);
            asm volatile("cp.async.wait_group 1;\n");
        } else {
            asm volatile("cp.async.wait_group 0;\n");
        }
        __syncthreads();

#pragma unroll
        for (int s = 0; s < 2; s++) {
            unsigned af[4][4];
#pragma unroll
            for (int i = 0; i < 4; i++)
                ldsm_x4(af[i], asb[p] + ((wm0 + 16 * i + lr) * ASU + lkc) * 4 + s * 32);
            unsigned bfr[4][2];
#pragma unroll
            for (int j = 0; j < 4; j++) {
                int col = wn0 + 8 * j + gid;
                bfr[j][0] = Bsp[p * 16 * BSU + (8 * s + tig) * BSU + col];
                bfr[j][1] = Bsp[p * 16 * BSU + (8 * s + tig + 4) * BSU + col];
            }
#pragma unroll
            for (int i = 0; i < 4; i++)
#pragma unroll
                for (int j = 0; j < 4; j++)
                    mma_bf16(acc[i][j], af[i], bfr[j], acc[i][j]);
        }
        p ^= 1;
    }

    __syncthreads();   // all MMA smem reads done; sbuf now reusable as hm

    // ---- epilogue ----
    bool theta_warp = (m0 == 0) && (wm0 == 0);
    if (theta_warp) {
        // theta rows -> Yh (bf16 pairs along n)
#pragma unroll
        for (int i = 0; i < 4; i++) {
            int r0 = 16 * i + gid;
#pragma unroll
            for (int j = 0; j < 4; j++) {
                int cc = n0 + wn0 + 8 * j + 2 * tig;
                *(unsigned*)&C[(size_t)r0 * N + cc]       = packbf(acc[i][j][0], acc[i][j][1]);
                *(unsigned*)&C[(size_t)(r0 + 8) * N + cc] = packbf(acc[i][j][2], acc[i][j][3]);
            }
        }
    } else {
        // pooled rows: stage horizontal max into hm[lrow][cc/2]
        int sub = (m0 == 0) ? 64 : 0;
#pragma unroll
        for (int i = 0; i < 4; i++) {
            int lr0 = wm0 + 16 * i + gid - sub;
#pragma unroll
            for (int j = 0; j < 4; j++) {
                int ch = (wn0 + 8 * j + 2 * tig) >> 1;     // 0..63
                hm[lr0 * HMS + ch]       = fmaxf(acc[i][j][0], acc[i][j][1]);
                hm[(lr0 + 8) * HMS + ch] = fmaxf(acc[i][j][2], acc[i][j][3]);
            }
        }
    }
    __syncthreads();

    if (m0 == 0) {
        // phi outputs: 32 d2 x 32 pw
        for (int o = tx; o < 1024; o += 256) {
            int pw = o & 31, d2 = o >> 5;
            float v0 = fmaxf(hm[(2 * d2) * HMS + pw],     hm[(2 * d2) * HMS + pw + 32]);
            float v1 = fmaxf(hm[(2 * d2 + 1) * HMS + pw], hm[(2 * d2 + 1) * HMS + pw + 32]);
            int mp = blockIdx.x * 32 + pw;
            int s = d2 >> 3, tg = d2 & 3, slot = (d2 >> 2) & 1;
            int sp = s >> 1, se = s & 1;
            int ln = (mp & 7) * 4 + tg, mblk = mp >> 3;
            g_phq[(((size_t)b * 2 + sp) * 128 + mblk) * 128 + ln * 4 + se * 2 + slot] =
                packbf(v0, v1);
        }
    } else {
        // g outputs: 128 v x 16 m2
        int vbase = m0 - 128;
        for (int o = tx; o < 2048; o += 256) {
            int pw2 = o & 15, vr = o >> 4;
            int pw = pw2 * 2;
            float v0 = fmaxf(hm[vr * HMS + pw],     hm[vr * HMS + pw + 32]);
            float v1 = fmaxf(hm[vr * HMS + pw + 1], hm[vr * HMS + pw + 33]);
            int v = vbase + vr;
            int m2 = blockIdx.x * 16 + pw2;
            int kk = m2 >> 3, tg = m2 & 3, slot = (m2 >> 2) & 1;
            int vblk = v >> 4, jj = (v >> 3) & 1, ln = (v & 7) * 4 + tg;
            g_gq[(((size_t)b * 64 + kk) * 16 + vblk) * 128 + ln * 4 + jj * 2 + slot] =
                packbf(v0, v1);
        }
    }
}

// ---------------- final GEMM: both operands bf16-packed, cp.async 2-stage ------
__global__ void __launch_bounds__(256, 2) gemm_async(
    const unsigned* __restrict__ A, const unsigned* __restrict__ Bbase,
    float* __restrict__ Cbase,
    int M, int K2, int N,
    const float* __restrict__ gamma, const float* __restrict__ resid)
{
    int b = blockIdx.z;
    const unsigned* B = Bbase + (size_t)b * K2 * N;
    float* C = Cbase + (size_t)b * M * N;
    int m0 = blockIdx.y * 128;
    int n0 = blockIdx.x * 128;

    __shared__ unsigned As[2][128 * ASU];
    __shared__ unsigned Bs[2][16 * BSU];

    int tx   = threadIdx.x;
    int wid  = tx >> 5;
    int lane = tx & 31;
    int gid  = lane >> 2;
    int tig  = lane & 3;
    int wm0  = (wid & 1) * 64;
    int wn0  = (wid >> 1) * 32;
    int lr   = (lane & 7) + ((lane >> 3) & 1) * 8;
    int lkc  = (lane >> 4) * 4;

    unsigned asb[2], bsb[2];
    asb[0] = (unsigned)__cvta_generic_to_shared(&As[0][0]);
    asb[1] = (unsigned)__cvta_generic_to_shared(&As[1][0]);
    bsb[0] = (unsigned)__cvta_generic_to_shared(&Bs[0][0]);
    bsb[1] = (unsigned)__cvta_generic_to_shared(&Bs[1][0]);

    float acc[4][4][4];
#pragma unroll
    for (int i = 0; i < 4; i++)
#pragma unroll
        for (int j = 0; j < 4; j++)
#pragma unroll
            for (int q = 0; q < 4; q++) acc[i][j][q] = 0.f;

    auto stage = [&](int k02, int p) {
#pragma unroll
        for (int r = 0; r < 2; r++) {
            int idx = tx + 256 * r;
            int am = idx >> 2, c4 = (idx & 3) * 4;
            CP16(asb[p] + (am * ASU + c4) * 4,
                 (const void*)&A[(size_t)(m0 + am) * K2 + k02 + c4]);
            int kr = idx >> 5, n4 = (idx & 31) * 4;
            CP16(bsb[p] + (kr * BSU + n4) * 4,
                 (const void*)&B[(size_t)(k02 + kr) * N + n0 + n4]);
        }
        asm volatile("cp.async.commit_group;\n");
    };

    stage(0, 0);
    int p = 0;
    for (int k02 = 0; k02 < K2; k02 += 16) {
        __syncthreads();
        bool nxt = (k02 + 16 < K2);
        if (nxt) {
            stage(k02 + 16, p ^ 1);
            asm volatile("cp.async.wait_group 1;\n");
        } else {
            asm volatile("cp.async.wait_group 0;\n");
        }
        __syncthreads();

#pragma unroll
        for (int s = 0; s < 2; s++) {
            unsigned af[4][4];
#pragma unroll
            for (int i = 0; i < 4; i++)
                ldsm_x4(af[i], asb[p] + ((wm0 + 16 * i + lr) * ASU + lkc) * 4 + s * 32);
            unsigned bfr[4][2];
#pragma unroll
            for (int j = 0; j < 4; j++) {
                int col = wn0 + 8 * j + gid;
                bfr[j][0] = Bs[p][(8 * s + tig) * BSU + col];
                bfr[j][1] = Bs[p][(8 * s + tig + 4) * BSU + col];
            }
#pragma unroll
            for (int i = 0; i < 4; i++)
#pragma unroll
                for (int j = 0; j < 4; j++)
                    mma_bf16(acc[i][j], af[i], bfr[j], acc[i][j]);
        }
        p ^= 1;
    }

    float gm = gamma[0];
#pragma unroll
    for (int i = 0; i < 4; i++) {
        int r0 = m0 + wm0 + 16 * i + gid;
#pragma unroll
        for (int j = 0; j < 4; j++) {
            int cc = n0 + wn0 + 8 * j + 2 * tig;
            const float* rr0 = resid + (size_t)b * M * N + (size_t)r0 * N + cc;
            const float* rr1 = rr0 + 8 * N;
            float2 v0 = make_float2(gm * acc[i][j][0] + rr0[0], gm * acc[i][j][1] + rr0[1]);
            float2 v1 = make_float2(gm * acc[i][j][2] + rr1[0], gm * acc[i][j][3] + rr1[1]);
            *(float2*)&C[(size_t)r0 * N + cc]       = v0;
            *(float2*)&C[(size_t)(r0 + 8) * N + cc] = v1;
        }
    }
}

// ---------------- fused attention: fused row-max in phase 1 ----------------
// smem (u32): S32[32][516] | ts[32][36] | sinv[32] | pmax[8][32]
#define S32S 516
#define TSS  36
#define ATTN_SMEM ((32 * S32S + 32 * TSS + 32 + 256) * 4)

__global__ void __launch_bounds__(256, 3) attn_kernel()
{
    extern __shared__ unsigned smu[];
    unsigned* S32  = smu;
    unsigned* ts   = smu + 32 * S32S;
    float*    sinv = (float*)(ts + 32 * TSS);
    float*    pmax = sinv + 32;           // [warp][row]

    int b    = blockIdx.y;
    int n0g  = blockIdx.x * 32;
    int tx   = threadIdx.x;
    int wid  = tx >> 5;
    int lane = tx & 31;
    int gid  = lane >> 2;
    int tig  = lane & 3;
    int lr   = (lane & 7) + ((lane >> 3) & 1) * 8;
    int lkc  = (lane >> 4) * 4;

    unsigned ts_sb  = (unsigned)__cvta_generic_to_shared(ts);
    unsigned s32_sb = (unsigned)__cvta_generic_to_shared(S32);

    // theta tile [n][d2] from bf16 Y (bit-pack, no re-round)
    {
        const __nv_bfloat16* Yb = g_Yh + (size_t)b * 384 * NPIX;
        for (int l = tx; l < 32 * 32; l += 256) {
            int n = l & 31, d2 = l >> 5;
            unsigned lo = *(const unsigned short*)&Yb[(size_t)(2 * d2) * NPIX + n0g + n];
            unsigned hi = *(const unsigned short*)&Yb[(size_t)(2 * d2 + 1) * NPIX + n0g + n];
            ts[n * TSS + d2] = lo | (hi << 16);
        }
    }
    __syncthreads();

    // ---- phase 1: S = theta^T phi; per-thread running row max ----
    {
        const uint4* PH4 = (const uint4*)g_phq + (size_t)b * 8192;
        unsigned a_all[4][2][4];
#pragma unroll
        for (int s = 0; s < 4; s++)
#pragma unroll
            for (int i = 0; i < 2; i++)
                ldsm_x4(a_all[s][i], ts_sb + ((16 * i + lr) * TSS + s * 8 + lkc) * 4);

        float rmax[4] = {-1e30f, -1e30f, -1e30f, -1e30f};

#pragma unroll 2
        for (int mj = 0; mj < 16; mj++) {
            int mblk = wid * 16 + mj;
            uint4 Q0 = PH4[(size_t)mblk * 32 + lane];            // sp=0: s=0,1
            uint4 Q1 = PH4[(size_t)(128 + mblk) * 32 + lane];    // sp=1: s=2,3
            float sa0[4] = {0.f, 0.f, 0.f, 0.f};
            float sa1[4] = {0.f, 0.f, 0.f, 0.f};
            {
                unsigned bfr[2] = {Q0.x, Q0.y};
                mma_bf16(sa0, a_all[0][0], bfr, sa0);
                mma_bf16(sa1, a_all[0][1], bfr, sa1);
            }
            {
                unsigned bfr[2] = {Q0.z, Q0.w};
                mma_bf16(sa0, a_all[1][0], bfr, sa0);
                mma_bf16(sa1, a_all[1][1], bfr, sa1);
            }
            {
                unsigned bfr[2] = {Q1.x, Q1.y};
                mma_bf16(sa0, a_all[2][0], bfr, sa0);
                mma_bf16(sa1, a_all[2][1], bfr, sa1);
            }
            {
                unsigned bfr[2] = {Q1.z, Q1.w};
                mma_bf16(sa0, a_all[3][0], bfr, sa0);
                mma_bf16(sa1, a_all[3][1], bfr, sa1);
            }
            rmax[0] = fmaxf(rmax[0], fmaxf(sa0[0], sa0[1]));
            rmax[1] = fmaxf(rmax[1], fmaxf(sa0[2], sa0[3]));
            rmax[2] = fmaxf(rmax[2], fmaxf(sa1[0], sa1[1]));
            rmax[3] = fmaxf(rmax[3], fmaxf(sa1[2], sa1[3]));

            int cc2 = wid * 64 + 4 * mj + tig;
            S32[gid * S32S + cc2]        = packbf(sa0[0], sa0[1]);
            S32[(gid + 8) * S32S + cc2]  = packbf(sa0[2], sa0[3]);
            S32[(gid + 16) * S32S + cc2] = packbf(sa1[0], sa1[1]);
            S32[(gid + 24) * S32S + cc2] = packbf(sa1[2], sa1[3]);
        }
        // reduce over the 4 tig-lanes of each row
#pragma unroll
        for (int q = 0; q < 4; q++) {
            rmax[q] = fmaxf(rmax[q], __shfl_xor_sync(0xFFFFFFFFu, rmax[q], 1));
            rmax[q] = fmaxf(rmax[q], __shfl_xor_sync(0xFFFFFFFFu, rmax[q], 2));
        }
        if (tig == 0) {
            pmax[wid * 32 + gid]      = rmax[0];
            pmax[wid * 32 + gid + 8]  = rmax[1];
            pmax[wid * 32 + gid + 16] = rmax[2];
            pmax[wid * 32 + gid + 24] = rmax[3];
        }
    }
    __syncthreads();

    // ---- phase 2: softmax exp pass (max pre-computed) ----
    {
        for (int rr = wid * 4; rr < wid * 4 + 4; rr++) {
            unsigned* row = S32 + rr * S32S;
            float mx = -1e30f;
#pragma unroll
            for (int w = 0; w < 8; w++) mx = fmaxf(mx, pmax[w * 32 + rr]);
            float sum = 0.f;
            for (int i = lane; i < 512; i += 32) {
                float2 v = unpackbf(row[i]);
                float e0 = __expf(v.x - mx);
                float e1 = __expf(v.y - mx);
                sum += e0 + e1;
                row[i] = packbf(e0, e1);
            }
#pragma unroll
            for (int off = 16; off; off >>= 1)
                sum += __shfl_xor_sync(0xFFFFFFFFu, sum, off);
            if (lane == 0) sinv[rr] = 1.f / sum;
        }
    }
    __syncthreads();

    // ---- phase 3: O = P @ g; warp wid owns v-range [wid*32, wid*32+32) ----
    {
        const uint4* G4 = (const uint4*)g_gq + (size_t)b * 32768;
        int wv0 = wid * 32;
        float acc3[2][4][4];
#pragma unroll
        for (int i = 0; i < 2; i++)
#pragma unroll
            for (int j = 0; j < 4; j++)
#pragma unroll
                for (int q = 0; q < 4; q++) acc3[i][j][q] = 0.f;

        unsigned a_addr0 = s32_sb + (lr * S32S + lkc) * 4;
        unsigned a_addr1 = s32_sb + ((16 + lr) * S32S + lkc) * 4;

#pragma unroll 4
        for (int kk = 0; kk < 64; kk++) {
            uint4 Q0 = G4[(size_t)kk * 512 + (wid * 2) * 32 + lane];      // j=0,1
            uint4 Q1 = G4[(size_t)kk * 512 + (wid * 2 + 1) * 32 + lane];  // j=2,3
            unsigned af0[4], af1[4];
            ldsm_x4(af0, a_addr0 + kk * 32);
            ldsm_x4(af1, a_addr1 + kk * 32);
            {
                unsigned bfr[2] = {Q0.x, Q0.y};
                mma_bf16(acc3[0][0], af0, bfr, acc3[0][0]);
                mma_bf16(acc3[1][0], af1, bfr, acc3[1][0]);
            }
            {
                unsigned bfr[2] = {Q0.z, Q0.w};
                mma_bf16(acc3[0][1], af0, bfr, acc3[0][1]);
                mma_bf16(acc3[1][1], af1, bfr, acc3[1][1]);
            }
            {
                unsigned bfr[2] = {Q1.x, Q1.y};
                mma_bf16(acc3[0][2], af0, bfr, acc3[0][2]);
                mma_bf16(acc3[1][2], af1, bfr, acc3[1][2]);
            }
            {
                unsigned bfr[2] = {Q1.z, Q1.w};
                mma_bf16(acc3[0][3], af0, bfr, acc3[0][3]);
                mma_bf16(acc3[1][3], af1, bfr, acc3[1][3]);
            }
        }
        __syncthreads();   // all warps done reading S32

        // stage O^T (fp32, stride 36) scaled by 1/sum
        float* St = (float*)S32;
#pragma unroll
        for (int i = 0; i < 2; i++) {
            int nn = 16 * i + gid;
            float s0 = sinv[nn];
            float s1 = sinv[nn + 8];
#pragma unroll
            for (int j = 0; j < 4; j++) {
                int vv = wv0 + 8 * j + 2 * tig;
                St[vv * 36 + nn]           = acc3[i][j][0] * s0;
                St[(vv + 1) * 36 + nn]     = acc3[i][j][1] * s0;
                St[vv * 36 + nn + 8]       = acc3[i][j][2] * s1;
                St[(vv + 1) * 36 + nn + 8] = acc3[i][j][3] * s1;
            }
        }
        __syncthreads();

        // packed bf16x2 output [b][v2][n]
        unsigned* ob = g_Ob + (size_t)b * 128 * NPIX;
        for (int it = 0; it < 16; it++) {
            int v2 = wid + 8 * it;
            ob[(size_t)v2 * NPIX + n0g + lane] =
                packbf(St[(2 * v2) * 36 + lane], St[(2 * v2 + 1) * 36 + lane]);
        }
    }
}

// ---------------- launch ----------------
extern "C" void kernel_launch(void* const* d_in, const int* in_sizes, int n_in,
                              void* d_out, int out_size)
{
    const float* x      = (const float*)d_in[0];
    const float* wtheta = (const float*)d_in[1];
    const float* wphi   = (const float*)d_in[2];
    const float* wg     = (const float*)d_in[3];
    const float* wo     = (const float*)d_in[4];
    const float* gamma  = (const float*)d_in[5];
    float* out = (float*)d_out;

    unsigned *dWb, *dWob, *dOb;
    __nv_bfloat16* dYh;
    cudaGetSymbolAddress((void**)&dWb,  g_Wb);
    cudaGetSymbolAddress((void**)&dWob, g_Wob);
    cudaGetSymbolAddress((void**)&dYh,  g_Yh);
    cudaGetSymbolAddress((void**)&dOb,  g_Ob);

    cudaFuncSetAttribute(attn_kernel,
                         cudaFuncAttributeMaxDynamicSharedMemorySize, ATTN_SMEM);

    // 1) weights -> bf16 pairs
    wcvt_kernel<<<(384 * 256 + 512 * 128 + 255) / 256, 256>>>(wtheta, wphi, wg, wo);

    // 2) projections + fused pool: Yh (theta) + g_phq/g_gq direct
    {
        dim3 grid(NPIX / 128, 384 / 128, BATCH);
        gemm_proj<<<grid, 256>>>(dWb, x, dYh, 384, 256, NPIX);
    }

    // 3) fused attention -> packed o
    {
        dim3 grid(NPIX / 32, BATCH);
        attn_kernel<<<grid, 256, ATTN_SMEM>>>();
    }

    // 4) out = gamma * (w_o @ o) + x   (M=512, K2=128, N=4096)
    {
        dim3 grid(NPIX / 128, 512 / 128, BATCH);
        gemm_async<<<grid, 256>>>(dWob, dOb, out, 512, 128, NPIX, gamma, x);
    }
}

// round 17
// speedup vs baseline: 1.2066x; 1.0271x over previous
#include <cuda_runtime.h>
#include <cuda_bf16.h>

#define BATCH 16
#define NPIX  4096   // 64*64
#define MPIX  1024   // 32*32

// ---------------- scratch (device globals; no allocation) ----------------
__device__ unsigned g_Wb[384 * 256];                            // [theta;phi;g] bf16x2 k-pairs
__device__ unsigned g_Wob[512 * 128];                           // w_o bf16x2 k-pairs
__device__ __nv_bfloat16 g_Yh[(size_t)BATCH * 384 * NPIX];      // theta rows (bf16)
__device__ __align__(16) unsigned g_phq[(size_t)BATCH * 32768]; // phi, uint4-frag layout
__device__ __align__(16) unsigned g_gq[(size_t)BATCH * 131072]; // g,   uint4-frag layout
__device__ unsigned g_Ob[(size_t)BATCH * 128 * NPIX];           // attn out bf16x2 [b][v2][n]

// ---------------- helpers ----------------
__device__ __forceinline__ unsigned packbf(float lo, float hi) {
    __nv_bfloat162 h = __floats2bfloat162_rn(lo, hi);
    return *(unsigned*)&h;
}
__device__ __forceinline__ float2 unpackbf(unsigned u) {
    __nv_bfloat162 h = *(__nv_bfloat162*)&u;
    return __bfloat1622float2(h);
}
__device__ __forceinline__ void mma_bf16(float* d, const unsigned* a, const unsigned* b,
                                         const float* c)
{
    asm volatile(
        "mma.sync.aligned.m16n8k16.row.col.f32.bf16.bf16.f32 "
        "{%0,%1,%2,%3}, {%4,%5,%6,%7}, {%8,%9}, {%10,%11,%12,%13};\n"
        : "=f"(d[0]), "=f"(d[1]), "=f"(d[2]), "=f"(d[3])
        : "r"(a[0]), "r"(a[1]), "r"(a[2]), "r"(a[3]),
          "r"(b[0]), "r"(b[1]),
          "f"(c[0]), "f"(c[1]), "f"(c[2]), "f"(c[3]));
}
__device__ __forceinline__ void ldsm_x4(unsigned* r, unsigned saddr) {
    asm volatile(
        "ldmatrix.sync.aligned.m8n8.x4.shared.b16 {%0,%1,%2,%3}, [%4];"
        : "=r"(r[0]), "=r"(r[1]), "=r"(r[2]), "=r"(r[3]) : "r"(saddr));
}
#define CP16(dst, src) \
    asm volatile("cp.async.cg.shared.global [%0], [%1], 16;\n" :: "r"(dst), "l"(src))

// ---------------- weight convert/concat -> bf16 pairs ----------------
__global__ void wcvt_kernel(const float* __restrict__ wt, const float* __restrict__ wp,
                            const float* __restrict__ wg, const float* __restrict__ wo)
{
    int t = blockIdx.x * blockDim.x + threadIdx.x;
    if (t < 384 * 256) {
        int row = t >> 8, k2 = t & 255;
        const float* src;
        if (row < 64)       src = wt + (size_t)row * 512;
        else if (row < 128) src = wp + (size_t)(row - 64) * 512;
        else                src = wg + (size_t)(row - 128) * 512;
        g_Wb[t] = packbf(src[2 * k2], src[2 * k2 + 1]);
    } else {
        int u = t - 384 * 256;
        if (u >= 512 * 128) return;
        int row = u >> 7, k2 = u & 127;
        g_Wob[u] = packbf(wo[(size_t)row * 256 + 2 * k2], wo[(size_t)row * 256 + 2 * k2 + 1]);
    }
}

#define ASU 20
#define BSU 136
#define HMS 65   // pooled-staging stride (floats)
#define GSTRIDE (128 * ASU + 16 * BSU)          // u32 per pipeline stage
#define GSMEM   (3 * GSTRIDE * 4)               // 3-stage dynamic smem bytes

// ---------------- projection GEMM + fused 2x2 maxpool epilogue ----------------
// m-tile 0: rows 0-63 theta -> Yh; rows 64-127 phi -> pooled g_phq
// m-tiles 1,2: g channels -> pooled g_gq
__global__ void __launch_bounds__(256, 2) gemm_proj(
    const unsigned* __restrict__ A, const float* __restrict__ Xbase,
    __nv_bfloat16* __restrict__ Cbase, int M, int K2, int N)
{
    // union: [As0|As1|Bs0|Bs1] during mainloop; hm[128][HMS] floats in epilogue
    __shared__ unsigned sbuf[2 * 128 * ASU + 2 * 16 * BSU];   // 37.9 KB >= 33.3 KB
    unsigned* Bsp = sbuf + 2 * 128 * ASU;
    float*    hm  = (float*)sbuf;

    int b = blockIdx.z;
    const float* X = Xbase + (size_t)b * (2 * K2) * N;
    __nv_bfloat16* C = Cbase + (size_t)b * M * N;
    int m0 = blockIdx.y * 128;
    int n0 = blockIdx.x * 128;

    int tx   = threadIdx.x;
    int wid  = tx >> 5;
    int lane = tx & 31;
    int gid  = lane >> 2;
    int tig  = lane & 3;
    int wm0  = (wid & 1) * 64;
    int wn0  = (wid >> 1) * 32;
    int lr   = (lane & 7) + ((lane >> 3) & 1) * 8;
    int lkc  = (lane >> 4) * 4;

    unsigned sb_base = (unsigned)__cvta_generic_to_shared(sbuf);
    unsigned asb[2];
    asb[0] = sb_base;
    asb[1] = sb_base + 128 * ASU * 4;

    int bkr[2], bn4[2];
#pragma unroll
    for (int r = 0; r < 2; r++) {
        int idx = tx + 256 * r;
        bkr[r] = idx >> 5;
        bn4[r] = (idx & 31) * 4;
    }

    float acc[4][4][4];
#pragma unroll
    for (int i = 0; i < 4; i++)
#pragma unroll
        for (int j = 0; j < 4; j++)
#pragma unroll
            for (int q = 0; q < 4; q++) acc[i][j][q] = 0.f;

    auto stageA = [&](int k02, int p) {
#pragma unroll
        for (int r = 0; r < 2; r++) {
            int idx = tx + 256 * r;
            int am = idx >> 2, c4 = (idx & 3) * 4;
            CP16(asb[p] + (am * ASU + c4) * 4,
                 (const void*)&A[(size_t)(m0 + am) * K2 + k02 + c4]);
        }
        asm volatile("cp.async.commit_group;\n");
    };
    auto ldgB = [&](int k02, float4* r0v, float4* r1v) {
#pragma unroll
        for (int r = 0; r < 2; r++) {
            const float* p0 = &X[(size_t)(2 * (k02 + bkr[r])) * N + n0 + bn4[r]];
            r0v[r] = *(const float4*)p0;
            r1v[r] = *(const float4*)(p0 + N);
        }
    };

    float4 b0[2], b1[2];
    ldgB(0, b0, b1);
    stageA(0, 0);
    int p = 0;
    for (int k02 = 0; k02 < K2; k02 += 16) {
        __syncthreads();
#pragma unroll
        for (int r = 0; r < 2; r++) {
            uint4 pv = make_uint4(packbf(b0[r].x, b1[r].x), packbf(b0[r].y, b1[r].y),
                                  packbf(b0[r].z, b1[r].z), packbf(b0[r].w, b1[r].w));
            *(uint4*)&Bsp[p * 16 * BSU + bkr[r] * BSU + bn4[r]] = pv;
        }
        bool nxt = (k02 + 16 < K2);
        if (nxt) {
            ldgB(k02 + 16, b0, b1);
            stageA(k02 + 16, p ^ 1);
            asm volatile("cp.async.wait_group 1;\n");
        } else {
            asm volatile("cp.async.wait_group 0;\n");
        }
        __syncthreads();

#pragma unroll
        for (int s = 0; s < 2; s++) {
            unsigned af[4][4];
#pragma unroll
            for (int i = 0; i < 4; i++)
                ldsm_x4(af[i], asb[p] + ((wm0 + 16 * i + lr) * ASU + lkc) * 4 + s * 32);
            unsigned bfr[4][2];
#pragma unroll
            for (int j = 0; j < 4; j++) {
                int col = wn0 + 8 * j + gid;
                bfr[j][0] = Bsp[p * 16 * BSU + (8 * s + tig) * BSU + col];
                bfr[j][1] = Bsp[p * 16 * BSU + (8 * s + tig + 4) * BSU + col];
            }
#pragma unroll
            for (int i = 0; i < 4; i++)
#pragma unroll
                for (int j = 0; j < 4; j++)
                    mma_bf16(acc[i][j], af[i], bfr[j], acc[i][j]);
        }
        p ^= 1;
    }

    __syncthreads();   // all MMA smem reads done; sbuf now reusable as hm

    // ---- epilogue ----
    bool theta_warp = (m0 == 0) && (wm0 == 0);
    if (theta_warp) {
        // theta rows -> Yh (bf16 pairs along n)
#pragma unroll
        for (int i = 0; i < 4; i++) {
            int r0 = 16 * i + gid;
#pragma unroll
            for (int j = 0; j < 4; j++) {
                int cc = n0 + wn0 + 8 * j + 2 * tig;
                *(unsigned*)&C[(size_t)r0 * N + cc]       = packbf(acc[i][j][0], acc[i][j][1]);
                *(unsigned*)&C[(size_t)(r0 + 8) * N + cc] = packbf(acc[i][j][2], acc[i][j][3]);
            }
        }
    } else {
        // pooled rows: stage horizontal max into hm[lrow][cc/2]
        int sub = (m0 == 0) ? 64 : 0;
#pragma unroll
        for (int i = 0; i < 4; i++) {
            int lr0 = wm0 + 16 * i + gid - sub;
#pragma unroll
            for (int j = 0; j < 4; j++) {
                int ch = (wn0 + 8 * j + 2 * tig) >> 1;     // 0..63
                hm[lr0 * HMS + ch]       = fmaxf(acc[i][j][0], acc[i][j][1]);
                hm[(lr0 + 8) * HMS + ch] = fmaxf(acc[i][j][2], acc[i][j][3]);
            }
        }
    }
    __syncthreads();

    if (m0 == 0) {
        // phi outputs: 32 d2 x 32 pw
        for (int o = tx; o < 1024; o += 256) {
            int pw = o & 31, d2 = o >> 5;
            float v0 = fmaxf(hm[(2 * d2) * HMS + pw],     hm[(2 * d2) * HMS + pw + 32]);
            float v1 = fmaxf(hm[(2 * d2 + 1) * HMS + pw], hm[(2 * d2 + 1) * HMS + pw + 32]);
            int mp = blockIdx.x * 32 + pw;
            int s = d2 >> 3, tg = d2 & 3, slot = (d2 >> 2) & 1;
            int sp = s >> 1, se = s & 1;
            int ln = (mp & 7) * 4 + tg, mblk = mp >> 3;
            g_phq[(((size_t)b * 2 + sp) * 128 + mblk) * 128 + ln * 4 + se * 2 + slot] =
                packbf(v0, v1);
        }
    } else {
        // g outputs: 128 v x 16 m2
        int vbase = m0 - 128;
        for (int o = tx; o < 2048; o += 256) {
            int pw2 = o & 15, vr = o >> 4;
            int pw = pw2 * 2;
            float v0 = fmaxf(hm[vr * HMS + pw],     hm[vr * HMS + pw + 32]);
            float v1 = fmaxf(hm[vr * HMS + pw + 1], hm[vr * HMS + pw + 33]);
            int v = vbase + vr;
            int m2 = blockIdx.x * 16 + pw2;
            int kk = m2 >> 3, tg = m2 & 3, slot = (m2 >> 2) & 1;
            int vblk = v >> 4, jj = (v >> 3) & 1, ln = (v & 7) * 4 + tg;
            g_gq[(((size_t)b * 64 + kk) * 16 + vblk) * 128 + ln * 4 + jj * 2 + slot] =
                packbf(v0, v1);
        }
    }
}

// ---------------- final GEMM: bf16-packed, 3-stage cp.async ----------------
__global__ void __launch_bounds__(256, 2) gemm_async(
    const unsigned* __restrict__ A, const unsigned* __restrict__ Bbase,
    float* __restrict__ Cbase,
    int M, int K2, int N,
    const float* __restrict__ gamma, const float* __restrict__ resid)
{
    extern __shared__ unsigned sm3[];

    int b = blockIdx.z;
    const unsigned* B = Bbase + (size_t)b * K2 * N;
    float* C = Cbase + (size_t)b * M * N;
    int m0 = blockIdx.y * 128;
    int n0 = blockIdx.x * 128;

    int tx   = threadIdx.x;
    int wid  = tx >> 5;
    int lane = tx & 31;
    int gid  = lane >> 2;
    int tig  = lane & 3;
    int wm0  = (wid & 1) * 64;
    int wn0  = (wid >> 1) * 32;
    int lr   = (lane & 7) + ((lane >> 3) & 1) * 8;
    int lkc  = (lane >> 4) * 4;

    unsigned sb = (unsigned)__cvta_generic_to_shared(sm3);
    const int NT = K2 / 16;

    float acc[4][4][4];
#pragma unroll
    for (int i = 0; i < 4; i++)
#pragma unroll
        for (int j = 0; j < 4; j++)
#pragma unroll
            for (int q = 0; q < 4; q++) acc[i][j][q] = 0.f;

    auto stage = [&](int t) {
        if (t < NT) {
            int p = t % 3;
            unsigned ab = sb + p * GSTRIDE * 4;
            unsigned bb = ab + 128 * ASU * 4;
#pragma unroll
            for (int r = 0; r < 2; r++) {
                int idx = tx + 256 * r;
                int am = idx >> 2, c4 = (idx & 3) * 4;
                CP16(ab + (am * ASU + c4) * 4,
                     (const void*)&A[(size_t)(m0 + am) * K2 + t * 16 + c4]);
                int kr = idx >> 5, n4 = (idx & 31) * 4;
                CP16(bb + (kr * BSU + n4) * 4,
                     (const void*)&B[(size_t)(t * 16 + kr) * N + n0 + n4]);
            }
        }
        asm volatile("cp.async.commit_group;\n");
    };

    stage(0); stage(1);

    for (int t = 0; t < NT; t++) {
        int p = t % 3;
        unsigned ab = sb + p * GSTRIDE * 4;
        unsigned* Bsp = sm3 + p * GSTRIDE + 128 * ASU;
        __syncthreads();                 // done reading buffer (t+2)%3 (from iter t-1)
        stage(t + 2);
        asm volatile("cp.async.wait_group 2;\n");   // tile t arrived
        __syncthreads();

#pragma unroll
        for (int s = 0; s < 2; s++) {
            unsigned af[4][4];
#pragma unroll
            for (int i = 0; i < 4; i++)
                ldsm_x4(af[i], ab + ((wm0 + 16 * i + lr) * ASU + lkc) * 4 + s * 32);
            unsigned bfr[4][2];
#pragma unroll
            for (int j = 0; j < 4; j++) {
                int col = wn0 + 8 * j + gid;
                bfr[j][0] = Bsp[(8 * s + tig) * BSU + col];
                bfr[j][1] = Bsp[(8 * s + tig + 4) * BSU + col];
            }
#pragma unroll
            for (int i = 0; i < 4; i++)
#pragma unroll
                for (int j = 0; j < 4; j++)
                    mma_bf16(acc[i][j], af[i], bfr[j], acc[i][j]);
        }
    }

    float gm = gamma[0];
#pragma unroll
    for (int i = 0; i < 4; i++) {
        int r0 = m0 + wm0 + 16 * i + gid;
#pragma unroll
        for (int j = 0; j < 4; j++) {
            int cc = n0 + wn0 + 8 * j + 2 * tig;
            const float* rr0 = resid + (size_t)b * M * N + (size_t)r0 * N + cc;
            const float* rr1 = rr0 + 8 * N;
            float2 v0 = make_float2(gm * acc[i][j][0] + rr0[0], gm * acc[i][j][1] + rr0[1]);
            float2 v1 = make_float2(gm * acc[i][j][2] + rr1[0], gm * acc[i][j][3] + rr1[1]);
            *(float2*)&C[(size_t)r0 * N + cc]       = v0;
            *(float2*)&C[(size_t)(r0 + 8) * N + cc] = v1;
        }
    }
}

// ---------------- fused attention: fused row-max in phase 1 ----------------
// smem (u32): S32[32][516] | ts[32][36] | sinv[32] | pmax[8][32]
#define S32S 516
#define TSS  36
#define ATTN_SMEM ((32 * S32S + 32 * TSS + 32 + 256) * 4)

__global__ void __launch_bounds__(256, 3) attn_kernel()
{
    extern __shared__ unsigned smu[];
    unsigned* S32  = smu;
    unsigned* ts   = smu + 32 * S32S;
    float*    sinv = (float*)(ts + 32 * TSS);
    float*    pmax = sinv + 32;           // [warp][row]

    int b    = blockIdx.y;
    int n0g  = blockIdx.x * 32;
    int tx   = threadIdx.x;
    int wid  = tx >> 5;
    int lane = tx & 31;
    int gid  = lane >> 2;
    int tig  = lane & 3;
    int lr   = (lane & 7) + ((lane >> 3) & 1) * 8;
    int lkc  = (lane >> 4) * 4;

    unsigned ts_sb  = (unsigned)__cvta_generic_to_shared(ts);
    unsigned s32_sb = (unsigned)__cvta_generic_to_shared(S32);

    // theta tile [n][d2] from bf16 Y (bit-pack, no re-round)
    {
        const __nv_bfloat16* Yb = g_Yh + (size_t)b * 384 * NPIX;
        for (int l = tx; l < 32 * 32; l += 256) {
            int n = l & 31, d2 = l >> 5;
            unsigned lo = *(const unsigned short*)&Yb[(size_t)(2 * d2) * NPIX + n0g + n];
            unsigned hi = *(const unsigned short*)&Yb[(size_t)(2 * d2 + 1) * NPIX + n0g + n];
            ts[n * TSS + d2] = lo | (hi << 16);
        }
    }
    __syncthreads();

    // ---- phase 1: S = theta^T phi; per-thread running row max ----
    {
        const uint4* PH4 = (const uint4*)g_phq + (size_t)b * 8192;
        unsigned a_all[4][2][4];
#pragma unroll
        for (int s = 0; s < 4; s++)
#pragma unroll
            for (int i = 0; i < 2; i++)
                ldsm_x4(a_all[s][i], ts_sb + ((16 * i + lr) * TSS + s * 8 + lkc) * 4);

        float rmax[4] = {-1e30f, -1e30f, -1e30f, -1e30f};

#pragma unroll 2
        for (int mj = 0; mj < 16; mj++) {
            int mblk = wid * 16 + mj;
            uint4 Q0 = PH4[(size_t)mblk * 32 + lane];            // sp=0: s=0,1
            uint4 Q1 = PH4[(size_t)(128 + mblk) * 32 + lane];    // sp=1: s=2,3
            float sa0[4] = {0.f, 0.f, 0.f, 0.f};
            float sa1[4] = {0.f, 0.f, 0.f, 0.f};
            {
                unsigned bfr[2] = {Q0.x, Q0.y};
                mma_bf16(sa0, a_all[0][0], bfr, sa0);
                mma_bf16(sa1, a_all[0][1], bfr, sa1);
            }
            {
                unsigned bfr[2] = {Q0.z, Q0.w};
                mma_bf16(sa0, a_all[1][0], bfr, sa0);
                mma_bf16(sa1, a_all[1][1], bfr, sa1);
            }
            {
                unsigned bfr[2] = {Q1.x, Q1.y};
                mma_bf16(sa0, a_all[2][0], bfr, sa0);
                mma_bf16(sa1, a_all[2][1], bfr, sa1);
            }
            {
                unsigned bfr[2] = {Q1.z, Q1.w};
                mma_bf16(sa0, a_all[3][0], bfr, sa0);
                mma_bf16(sa1, a_all[3][1], bfr, sa1);
            }
            rmax[0] = fmaxf(rmax[0], fmaxf(sa0[0], sa0[1]));
            rmax[1] = fmaxf(rmax[1], fmaxf(sa0[2], sa0[3]));
            rmax[2] = fmaxf(rmax[2], fmaxf(sa1[0], sa1[1]));
            rmax[3] = fmaxf(rmax[3], fmaxf(sa1[2], sa1[3]));

            int cc2 = wid * 64 + 4 * mj + tig;
            S32[gid * S32S + cc2]        = packbf(sa0[0], sa0[1]);
            S32[(gid + 8) * S32S + cc2]  = packbf(sa0[2], sa0[3]);
            S32[(gid + 16) * S32S + cc2] = packbf(sa1[0], sa1[1]);
            S32[(gid + 24) * S32S + cc2] = packbf(sa1[2], sa1[3]);
        }
        // reduce over the 4 tig-lanes of each row
#pragma unroll
        for (int q = 0; q < 4; q++) {
            rmax[q] = fmaxf(rmax[q], __shfl_xor_sync(0xFFFFFFFFu, rmax[q], 1));
            rmax[q] = fmaxf(rmax[q], __shfl_xor_sync(0xFFFFFFFFu, rmax[q], 2));
        }
        if (tig == 0) {
            pmax[wid * 32 + gid]      = rmax[0];
            pmax[wid * 32 + gid + 8]  = rmax[1];
            pmax[wid * 32 + gid + 16] = rmax[2];
            pmax[wid * 32 + gid + 24] = rmax[3];
        }
    }
    __syncthreads();

    // ---- phase 2: softmax exp pass (max pre-computed) ----
    {
        for (int rr = wid * 4; rr < wid * 4 + 4; rr++) {
            unsigned* row = S32 + rr * S32S;
            float mx = -1e30f;
#pragma unroll
            for (int w = 0; w < 8; w++) mx = fmaxf(mx, pmax[w * 32 + rr]);
            float sum = 0.f;
            for (int i = lane; i < 512; i += 32) {
                float2 v = unpackbf(row[i]);
                float e0 = __expf(v.x - mx);
                float e1 = __expf(v.y - mx);
                sum += e0 + e1;
                row[i] = packbf(e0, e1);
            }
#pragma unroll
            for (int off = 16; off; off >>= 1)
                sum += __shfl_xor_sync(0xFFFFFFFFu, sum, off);
            if (lane == 0) sinv[rr] = 1.f / sum;
        }
    }
    __syncthreads();

    // ---- phase 3: O = P @ g; warp wid owns v-range [wid*32, wid*32+32) ----
    {
        const uint4* G4 = (const uint4*)g_gq + (size_t)b * 32768;
        int wv0 = wid * 32;
        float acc3[2][4][4];
#pragma unroll
        for (int i = 0; i < 2; i++)
#pragma unroll
            for (int j = 0; j < 4; j++)
#pragma unroll
                for (int q = 0; q < 4; q++) acc3[i][j][q] = 0.f;

        unsigned a_addr0 = s32_sb + (lr * S32S + lkc) * 4;
        unsigned a_addr1 = s32_sb + ((16 + lr) * S32S + lkc) * 4;

#pragma unroll 4
        for (int kk = 0; kk < 64; kk++) {
            uint4 Q0 = G4[(size_t)kk * 512 + (wid * 2) * 32 + lane];      // j=0,1
            uint4 Q1 = G4[(size_t)kk * 512 + (wid * 2 + 1) * 32 + lane];  // j=2,3
            unsigned af0[4], af1[4];
            ldsm_x4(af0, a_addr0 + kk * 32);
            ldsm_x4(af1, a_addr1 + kk * 32);
            {
                unsigned bfr[2] = {Q0.x, Q0.y};
                mma_bf16(acc3[0][0], af0, bfr, acc3[0][0]);
                mma_bf16(acc3[1][0], af1, bfr, acc3[1][0]);
            }
            {
                unsigned bfr[2] = {Q0.z, Q0.w};
                mma_bf16(acc3[0][1], af0, bfr, acc3[0][1]);
                mma_bf16(acc3[1][1], af1, bfr, acc3[1][1]);
            }
            {
                unsigned bfr[2] = {Q1.x, Q1.y};
                mma_bf16(acc3[0][2], af0, bfr, acc3[0][2]);
                mma_bf16(acc3[1][2], af1, bfr, acc3[1][2]);
            }
            {
                unsigned bfr[2] = {Q1.z, Q1.w};
                mma_bf16(acc3[0][3], af0, bfr, acc3[0][3]);
                mma_bf16(acc3[1][3], af1, bfr, acc3[1][3]);
            }
        }
        __syncthreads();   // all warps done reading S32

        // stage O^T (fp32, stride 36) scaled by 1/sum
        float* St = (float*)S32;
#pragma unroll
        for (int i = 0; i < 2; i++) {
            int nn = 16 * i + gid;
            float s0 = sinv[nn];
            float s1 = sinv[nn + 8];
#pragma unroll
            for (int j = 0; j < 4; j++) {
                int vv = wv0 + 8 * j + 2 * tig;
                St[vv * 36 + nn]           = acc3[i][j][0] * s0;
                St[(vv + 1) * 36 + nn]     = acc3[i][j][1] * s0;
                St[vv * 36 + nn + 8]       = acc3[i][j][2] * s1;
                St[(vv + 1) * 36 + nn + 8] = acc3[i][j][3] * s1;
            }
        }
        __syncthreads();

        // packed bf16x2 output [b][v2][n]
        unsigned* ob = g_Ob + (size_t)b * 128 * NPIX;
        for (int it = 0; it < 16; it++) {
            int v2 = wid + 8 * it;
            ob[(size_t)v2 * NPIX + n0g + lane] =
                packbf(St[(2 * v2) * 36 + lane], St[(2 * v2 + 1) * 36 + lane]);
        }
    }
}

// ---------------- launch ----------------
extern "C" void kernel_launch(void* const* d_in, const int* in_sizes, int n_in,
                              void* d_out, int out_size)
{
    const float* x      = (const float*)d_in[0];
    const float* wtheta = (const float*)d_in[1];
    const float* wphi   = (const float*)d_in[2];
    const float* wg     = (const float*)d_in[3];
    const float* wo     = (const float*)d_in[4];
    const float* gamma  = (const float*)d_in[5];
    float* out = (float*)d_out;

    unsigned *dWb, *dWob, *dOb;
    __nv_bfloat16* dYh;
    cudaGetSymbolAddress((void**)&dWb,  g_Wb);
    cudaGetSymbolAddress((void**)&dWob, g_Wob);
    cudaGetSymbolAddress((void**)&dYh,  g_Yh);
    cudaGetSymbolAddress((void**)&dOb,  g_Ob);

    cudaFuncSetAttribute(attn_kernel,
                         cudaFuncAttributeMaxDynamicSharedMemorySize, ATTN_SMEM);
    cudaFuncSetAttribute(gemm_async,
                         cudaFuncAttributeMaxDynamicSharedMemorySize, GSMEM);

    // 1) weights -> bf16 pairs
    wcvt_kernel<<<(384 * 256 + 512 * 128 + 255) / 256, 256>>>(wtheta, wphi, wg, wo);

    // 2) projections + fused pool: Yh (theta) + g_phq/g_gq direct
    {
        dim3 grid(NPIX / 128, 384 / 128, BATCH);
        gemm_proj<<<grid, 256>>>(dWb, x, dYh, 384, 256, NPIX);
    }

    // 3) fused attention -> packed o
    {
        dim3 grid(NPIX / 32, BATCH);
        attn_kernel<<<grid, 256, ATTN_SMEM>>>();
    }

    // 4) out = gamma * (w_o @ o) + x   (M=512, K2=128, N=4096)
    {
        dim3 grid(NPIX / 128, 512 / 128, BATCH);
        gemm_async<<<grid, 256, GSMEM>>>(dWob, dOb, out, 512, 128, NPIX, gamma, x);
    }
}